// round 8
// baseline (speedup 1.0000x reference)
#include <cuda_runtime.h>
#include <cuda_fp16.h>
#include <cstdint>

#define N_NODES 100000
#define N_EDGES 1600000
#define DD 64

typedef unsigned long long u64;

// ------------------- scratch (static device globals; no allocation) -------------------
__device__ float g_x1[(size_t)N_NODES * DD];        // x@W1^T+b1
__device__ float g_x3[(size_t)N_NODES * DD];        // x@W3^T+b3
__device__ float g_x24[(size_t)N_NODES * 2 * DD];   // per node: [x2 row | x4 row]
__device__ float g_y[(size_t)N_NODES * DD];         // x1 + aggregated (pre-BN node)
__device__ float g_sums[(size_t)N_NODES * DD];      // scatter-add accumulator
__device__ float g_cnt[N_NODES];                    // per-src edge counts
__device__ __half g_t[(size_t)N_EDGES * DD];        // pre-BN edge tensor (fp16, 204.8 MB)
__device__ float g_WtN[64 * 256];                   // k-major stacked [W1|W2|W3|W4]
__device__ float g_bN[256];
__device__ float g_WtE[64 * 64];                    // k-major We
__device__ float g_nstat[128];                      // node: sum[64], ssq[64]
__device__ float g_estat[128];                      // edge: sum[64], ssq[64]

// ------------------- helpers -------------------
__device__ __forceinline__ u64 pack2(float lo, float hi) {
    u64 r; unsigned a = __float_as_uint(lo), b = __float_as_uint(hi);
    asm("mov.b64 %0, {%1,%2};" : "=l"(r) : "r"(a), "r"(b));
    return r;
}
__device__ __forceinline__ u64 bcast2(float v) {
    u64 r; unsigned a = __float_as_uint(v);
    asm("mov.b64 %0, {%1,%1};" : "=l"(r) : "r"(a));
    return r;
}
__device__ __forceinline__ void fma2(u64& d, u64 a, u64 b) {
    asm("fma.rn.f32x2 %0, %1, %2, %0;" : "+l"(d) : "l"(a), "l"(b));
}
__device__ __forceinline__ float2 unpack2(u64 v) {
    unsigned lo, hi;
    asm("mov.b64 {%0,%1}, %2;" : "=r"(lo), "=r"(hi) : "l"(v));
    return make_float2(__uint_as_float(lo), __uint_as_float(hi));
}
__device__ __forceinline__ float sigmoidf(float x) { return 1.0f / (1.0f + __expf(-x)); }

__device__ __forceinline__ unsigned sm2u(const void* p) {
    return (unsigned)__cvta_generic_to_shared(p);
}
__device__ __forceinline__ u64 mkpolicy_evict_first() {
    u64 p;
    asm("createpolicy.fractional.L2::evict_first.b64 %0, 1.0;" : "=l"(p));
    return p;
}
__device__ __forceinline__ void cpa16(unsigned s, const void* g) {
    asm volatile("cp.async.cg.shared.global [%0], [%1], 16;" :: "r"(s), "l"(g));
}
__device__ __forceinline__ void cpa16_pol(unsigned s, const void* g, u64 pol) {
    asm volatile("cp.async.cg.shared.global.L2::cache_hint [%0], [%1], 16, %2;"
                 :: "r"(s), "l"(g), "l"(pol));
}
__device__ __forceinline__ void cpa_commit() {
    asm volatile("cp.async.commit_group;");
}
__device__ __forceinline__ void cpa_wait0() {
    asm volatile("cp.async.wait_group 0;");
}
__device__ __forceinline__ void red4(float* p, float a, float b, float c, float d) {
    asm volatile("red.global.add.v4.f32 [%0], {%1,%2,%3,%4};"
                 :: "l"(p), "f"(a), "f"(b), "f"(c), "f"(d) : "memory");
}
__device__ __forceinline__ void st8_cs(__half* p, unsigned a, unsigned b) {
    asm volatile("st.global.cs.v2.b32 [%0], {%1,%2};" :: "l"(p), "r"(a), "r"(b) : "memory");
}

// ------------------- kernel 1: transpose weights to k-major (+ zero stats) -------------------
__global__ void prepack(const float* __restrict__ W1, const float* __restrict__ W2,
                        const float* __restrict__ W3, const float* __restrict__ W4,
                        const float* __restrict__ We, const float* __restrict__ b1,
                        const float* __restrict__ b2, const float* __restrict__ b3,
                        const float* __restrict__ b4) {
    int t = blockIdx.x * blockDim.x + threadIdx.x;
    if (t < 4096) {
        int j = t >> 6, k = t & 63;
        int o = k * 256 + j;
        g_WtN[o]       = W1[t];
        g_WtN[o + 64]  = W2[t];
        g_WtN[o + 128] = W3[t];
        g_WtN[o + 192] = W4[t];
        g_WtE[k * 64 + j] = We[t];
    }
    if (t < 64) {
        g_bN[t] = b1[t]; g_bN[64 + t] = b2[t]; g_bN[128 + t] = b3[t]; g_bN[192 + t] = b4[t];
    }
    if (t < 128) { g_nstat[t] = 0.0f; g_estat[t] = 0.0f; }
}

// ------------------- kernel 2: node GEMMs (x1..x4 fused, f32x2) + zero sums -------------------
#define NODE_SMEM ((16384 + 32 * 68 + 256) * 4)
__global__ __launch_bounds__(256, 2) void node_gemm(const float* __restrict__ x) {
    extern __shared__ float sm[];
    float* WtS = sm;
    float* xs  = sm + 16384;
    float* bS  = sm + 16384 + 2176;
    int tid = threadIdx.x;
    for (int i = tid; i < 16384; i += 256) WtS[i] = g_WtN[i];
    bS[tid] = g_bN[tid];
    __syncthreads();

    int c32 = tid & 31, rg = tid >> 5;
    int j0 = c32 * 4, j1 = 128 + c32 * 4;
    u64 biasv[4] = { pack2(bS[j0], bS[j0 + 1]), pack2(bS[j0 + 2], bS[j0 + 3]),
                     pack2(bS[j1], bS[j1 + 1]), pack2(bS[j1 + 2], bS[j1 + 3]) };

    const float4 z4 = make_float4(0.f, 0.f, 0.f, 0.f);
    const int NT = N_NODES / 32;
    for (int tile = blockIdx.x; tile < NT; tile += gridDim.x) {
        int base = tile * 32;
        const float4* gp = (const float4*)(x + (size_t)base * DD);
        for (int f = tid; f < 512; f += 256) {
            float4 v = gp[f];
            int row = f >> 4, c4 = f & 15;
            *(float4*)&xs[row * 68 + c4 * 4] = v;
            ((float4*)(g_sums + (size_t)base * 64))[f] = z4;
        }
        if (tid < 32) g_cnt[base + tid] = 0.0f;
        __syncthreads();

        u64 acc[4][4];
        #pragma unroll
        for (int rr = 0; rr < 4; rr++) {
            acc[rr][0] = biasv[0]; acc[rr][1] = biasv[1];
            acc[rr][2] = biasv[2]; acc[rr][3] = biasv[3];
        }
        #pragma unroll
        for (int k0 = 0; k0 < 64; k0 += 4) {
            float xr[4][4];
            #pragma unroll
            for (int rr = 0; rr < 4; rr++) {
                float4 a = *(const float4*)&xs[(rg + 8 * rr) * 68 + k0];
                xr[rr][0] = a.x; xr[rr][1] = a.y; xr[rr][2] = a.z; xr[rr][3] = a.w;
            }
            #pragma unroll
            for (int kk = 0; kk < 4; kk++) {
                int k = k0 + kk;
                ulonglong2 wa = *(const ulonglong2*)&WtS[k * 256 + j0];
                ulonglong2 wb = *(const ulonglong2*)&WtS[k * 256 + j1];
                #pragma unroll
                for (int rr = 0; rr < 4; rr++) {
                    u64 av = bcast2(xr[rr][kk]);
                    fma2(acc[rr][0], av, wa.x); fma2(acc[rr][1], av, wa.y);
                    fma2(acc[rr][2], av, wb.x); fma2(acc[rr][3], av, wb.y);
                }
            }
        }
        #pragma unroll
        for (int rr = 0; rr < 4; rr++) {
            int n = base + rg + 8 * rr;
            float2 a0 = unpack2(acc[rr][0]), a1 = unpack2(acc[rr][1]);
            float2 a2 = unpack2(acc[rr][2]), a3 = unpack2(acc[rr][3]);
            float4 vA = make_float4(a0.x, a0.y, a1.x, a1.y);
            float4 vB = make_float4(a2.x, a2.y, a3.x, a3.y);
            float* pA = (c32 < 16) ? &g_x1[(size_t)n * 64 + j0]
                                   : &g_x24[(size_t)n * 128 + (j0 - 64)];
            float* pB = (c32 < 16) ? &g_x3[(size_t)n * 64 + (j1 - 128)]
                                   : &g_x24[(size_t)n * 128 + 64 + (j1 - 192)];
            *(float4*)pA = vA;
            *(float4*)pB = vB;
        }
        __syncthreads();
    }
}

// ------------------- kernel 3: edge pass 1 (64-edge tiles, 3 blocks/SM) -------------------
// smem floats: WtS[4096] | w0s[2*4352] | beS[64] | sS[2*64]i | dS[2*64]i
#define W0S_OFF    4096
#define W0S_STRIDE 4352
#define BES_OFF    (4096 + 2 * 4352)     // 12800
#define IDX_OFF    (BES_OFF + 64)        // 12864
#define EDGE_SMEM  ((IDX_OFF + 256) * 4) // 52480 B
#define ETILE      64
#define ETILES     (N_EDGES / ETILE)     // 25000
#define EDGE_GRID  444                   // 148 SMs * 3 blocks

__device__ __forceinline__ void prefetch_tile(float* w0buf, int* sbuf, int* dbuf,
                                              const float* __restrict__ ea,
                                              const int* __restrict__ srcp,
                                              const int* __restrict__ dstp,
                                              int base, int tid, u64 pol) {
    if (tid < 16) {
        cpa16(sm2u(sbuf + tid * 4), srcp + base + tid * 4);
    } else if (tid < 32) {
        int i = tid - 16;
        cpa16(sm2u(dbuf + i * 4), dstp + base + i * 4);
    }
    const float4* gp = (const float4*)(ea + (size_t)base * DD);
    #pragma unroll
    for (int u = 0; u < 4; u++) {
        int f = tid + u * 256;                 // 1024 float4s = full 64x64 tile
        int row = f >> 4, c4 = f & 15;
        cpa16_pol(sm2u(w0buf + row * 68 + c4 * 4), gp + f, pol);
    }
}

__global__ __launch_bounds__(256, 3)
void edge_pass1(const float* __restrict__ ea, const int* __restrict__ srcp,
                const int* __restrict__ dstp, const float* __restrict__ be) {
    extern __shared__ float sm[];
    float* WtS = sm;
    float* beS = sm + BES_OFF;
    int* sS = (int*)(sm + IDX_OFF);        // 2 x 64
    int* dS = sS + 128;                    // 2 x 64

    int tid = threadIdx.x;
    u64 pol = mkpolicy_evict_first();
    for (int i = tid; i < 4096; i += 256) WtS[i] = g_WtE[i];
    if (tid < 64) beS[tid] = be[tid];

    prefetch_tile(sm + W0S_OFF, sS, dS, ea, srcp, dstp, blockIdx.x * ETILE, tid, pol);
    cpa_commit();
    __syncthreads();

    int c8 = tid & 7, rq = tid >> 3;       // rq in [0,32): rows rq and rq+32
    int j0 = c8 * 4, j1 = 32 + c8 * 4;

    float ssum[8], sssq[8];
    #pragma unroll
    for (int i = 0; i < 8; i++) { ssum[i] = 0.0f; sssq[i] = 0.0f; }

    int buf = 0;
    for (int tile = blockIdx.x; tile < ETILES; tile += EDGE_GRID) {
        cpa_wait0();
        __syncthreads();
        float* w0c = sm + W0S_OFF + buf * W0S_STRIDE;
        int* sC = sS + buf * 64;
        int* dC = dS + buf * 64;
        int base = tile * ETILE;

        // ---- early gather for row rq (hidden under GEMV) ----
        int s_cur = sC[rq], d_cur = dC[rq];
        const float* x3p = g_x3 + (size_t)s_cur * 64;
        const float* x24p = g_x24 + (size_t)d_cur * 128;
        float4 p0 = *(const float4*)(x3p + j0);
        float4 p1 = *(const float4*)(x3p + j1);
        float4 p2 = *(const float4*)(x24p + j0);
        float4 p3 = *(const float4*)(x24p + j1);
        float4 p4 = *(const float4*)(x24p + 64 + j0);
        float4 p5 = *(const float4*)(x24p + 64 + j1);

        // ---- issue next tile's prefetch (overlaps GEMV) ----
        int ntile = tile + EDGE_GRID;
        if (ntile < ETILES)
            prefetch_tile(sm + W0S_OFF + (buf ^ 1) * W0S_STRIDE,
                          sS + (buf ^ 1) * 64, dS + (buf ^ 1) * 64,
                          ea, srcp, dstp, ntile * ETILE, tid, pol);
        cpa_commit();

        // ---- GEMV: w1 = w0 @ We^T + be (rows rq, rq+32) ----
        u64 acc[2][4];
        {
            ulonglong2 bA = *(const ulonglong2*)&beS[j0];
            ulonglong2 bB = *(const ulonglong2*)&beS[j1];
            #pragma unroll
            for (int rr = 0; rr < 2; rr++) {
                acc[rr][0] = bA.x; acc[rr][1] = bA.y;
                acc[rr][2] = bB.x; acc[rr][3] = bB.y;
            }
        }
        #pragma unroll
        for (int k0 = 0; k0 < 64; k0 += 4) {
            float w0r[2][4];
            #pragma unroll
            for (int rr = 0; rr < 2; rr++) {
                float4 a = *(const float4*)&w0c[(rq + 32 * rr) * 68 + k0];
                w0r[rr][0] = a.x; w0r[rr][1] = a.y; w0r[rr][2] = a.z; w0r[rr][3] = a.w;
            }
            #pragma unroll
            for (int kk = 0; kk < 4; kk++) {
                int k = k0 + kk;
                ulonglong2 wa = *(const ulonglong2*)&WtS[k * 64 + j0];
                ulonglong2 wb = *(const ulonglong2*)&WtS[k * 64 + j1];
                #pragma unroll
                for (int rr = 0; rr < 2; rr++) {
                    u64 av = bcast2(w0r[rr][kk]);
                    fma2(acc[rr][0], av, wa.x); fma2(acc[rr][1], av, wa.y);
                    fma2(acc[rr][2], av, wb.x); fma2(acc[rr][3], av, wb.y);
                }
            }
        }

        // ---- combine: 2 rows, 1-deep pipelined gathers ----
        #pragma unroll
        for (int rr = 0; rr < 2; rr++) {
            int row = rq + 32 * rr;
            float4 x3a = p0, x3b = p1, x2a = p2, x2b = p3, x4a = p4, x4b = p5;
            int s_use = s_cur;
            if (rr < 1) {
                int nrow = row + 32;
                s_cur = sC[nrow]; d_cur = dC[nrow];
                const float* nx3 = g_x3 + (size_t)s_cur * 64;
                const float* nx24 = g_x24 + (size_t)d_cur * 128;
                p0 = *(const float4*)(nx3 + j0);
                p1 = *(const float4*)(nx3 + j1);
                p2 = *(const float4*)(nx24 + j0);
                p3 = *(const float4*)(nx24 + j1);
                p4 = *(const float4*)(nx24 + 64 + j0);
                p5 = *(const float4*)(nx24 + 64 + j1);
            }

            float2 w1_0 = unpack2(acc[rr][0]), w1_1 = unpack2(acc[rr][1]);
            float2 w1_2 = unpack2(acc[rr][2]), w1_3 = unpack2(acc[rr][3]);
            float tv[8];
            tv[0] = w1_0.x + x3a.x + x4a.x;
            tv[1] = w1_0.y + x3a.y + x4a.y;
            tv[2] = w1_1.x + x3a.z + x4a.z;
            tv[3] = w1_1.y + x3a.w + x4a.w;
            tv[4] = w1_2.x + x3b.x + x4b.x;
            tv[5] = w1_2.y + x3b.y + x4b.y;
            tv[6] = w1_3.x + x3b.z + x4b.z;
            tv[7] = w1_3.y + x3b.w + x4b.w;
            size_t eb = (size_t)(base + row) * 64;
            __half2 ha = __floats2half2_rn(tv[0], tv[1]);
            __half2 hb = __floats2half2_rn(tv[2], tv[3]);
            __half2 hc = __floats2half2_rn(tv[4], tv[5]);
            __half2 hd = __floats2half2_rn(tv[6], tv[7]);
            st8_cs(&g_t[eb + j0], *(unsigned*)&ha, *(unsigned*)&hb);
            st8_cs(&g_t[eb + j1], *(unsigned*)&hc, *(unsigned*)&hd);
            #pragma unroll
            for (int i = 0; i < 8; i++) {
                ssum[i] += tv[i];
                sssq[i] = fmaf(tv[i], tv[i], sssq[i]);
            }
            float4 wva = *(const float4*)&w0c[row * 68 + j0];
            float4 wvb = *(const float4*)&w0c[row * 68 + j1];
            float* sp = g_sums + (size_t)s_use * 64;
            red4(sp + j0, sigmoidf(wva.x) * x2a.x, sigmoidf(wva.y) * x2a.y,
                          sigmoidf(wva.z) * x2a.z, sigmoidf(wva.w) * x2a.w);
            red4(sp + j1, sigmoidf(wvb.x) * x2b.x, sigmoidf(wvb.y) * x2b.y,
                          sigmoidf(wvb.z) * x2b.z, sigmoidf(wvb.w) * x2b.w);
            if (c8 == 0) atomicAdd(&g_cnt[s_use], 1.0f);
        }
        buf ^= 1;
    }

    // ---- flush BN stats: warp shfl -> smem block reduction -> 128 atomics/block ----
    #pragma unroll
    for (int i = 0; i < 8; i++) {
        ssum[i] += __shfl_xor_sync(0xffffffffu, ssum[i], 8);
        ssum[i] += __shfl_xor_sync(0xffffffffu, ssum[i], 16);
        sssq[i] += __shfl_xor_sync(0xffffffffu, sssq[i], 8);
        sssq[i] += __shfl_xor_sync(0xffffffffu, sssq[i], 16);
    }
    __syncthreads();               // main loop done in all warps; WtS region now reusable
    float* redb = sm;              // [8 warps][128 stats]
    int warp = tid >> 5, lane = tid & 31;
    if ((lane & 24) == 0) {        // lanes 0..7: hold the 8 col-values for this c8
        #pragma unroll
        for (int i = 0; i < 8; i++) {
            int col = (i < 4) ? (j0 + i) : (j1 + i - 4);
            redb[warp * 128 + col] = ssum[i];
            redb[warp * 128 + 64 + col] = sssq[i];
        }
    }
    __syncthreads();
    if (tid < 128) {
        float v = 0.0f;
        #pragma unroll
        for (int w = 0; w < 8; w++) v += redb[w * 128 + tid];
        atomicAdd(&g_estat[tid], v);
    }
}

// ------------------- kernel 4: node pre-BN + stats (smem-reduced atomics) -------------------
#define NS_BLOCKS 512
__global__ void node_stats() {
    __shared__ float redb[8 * 128];
    int tid = threadIdx.x;
    int t = blockIdx.x * 256 + tid;
    int c = (tid & 15) * 4;
    int stride = (NS_BLOCKS * 256) >> 4;
    float s0 = 0, s1 = 0, s2 = 0, s3 = 0, q0 = 0, q1 = 0, q2 = 0, q3 = 0;
    for (int n = t >> 4; n < N_NODES; n += stride) {
        size_t off = (size_t)n * 64 + c;
        float4 a = *(const float4*)&g_x1[off];
        float4 g = *(const float4*)&g_sums[off];
        float inv = 1.0f / fmaxf(g_cnt[n], 1.0f);
        float4 y;
        y.x = fmaf(g.x, inv, a.x);
        y.y = fmaf(g.y, inv, a.y);
        y.z = fmaf(g.z, inv, a.z);
        y.w = fmaf(g.w, inv, a.w);
        *(float4*)&g_y[off] = y;
        s0 += y.x; q0 = fmaf(y.x, y.x, q0);
        s1 += y.y; q1 = fmaf(y.y, y.y, q1);
        s2 += y.z; q2 = fmaf(y.z, y.z, q2);
        s3 += y.w; q3 = fmaf(y.w, y.w, q3);
    }
    s0 += __shfl_xor_sync(0xffffffffu, s0, 16);
    s1 += __shfl_xor_sync(0xffffffffu, s1, 16);
    s2 += __shfl_xor_sync(0xffffffffu, s2, 16);
    s3 += __shfl_xor_sync(0xffffffffu, s3, 16);
    q0 += __shfl_xor_sync(0xffffffffu, q0, 16);
    q1 += __shfl_xor_sync(0xffffffffu, q1, 16);
    q2 += __shfl_xor_sync(0xffffffffu, q2, 16);
    q3 += __shfl_xor_sync(0xffffffffu, q3, 16);
    int warp = tid >> 5, lane = tid & 31;
    if (lane < 16) {
        redb[warp * 128 + c + 0] = s0;
        redb[warp * 128 + c + 1] = s1;
        redb[warp * 128 + c + 2] = s2;
        redb[warp * 128 + c + 3] = s3;
        redb[warp * 128 + 64 + c + 0] = q0;
        redb[warp * 128 + 64 + c + 1] = q1;
        redb[warp * 128 + 64 + c + 2] = q2;
        redb[warp * 128 + 64 + c + 3] = q3;
    }
    __syncthreads();
    if (tid < 128) {
        float v = 0.0f;
        #pragma unroll
        for (int w = 0; w < 8; w++) v += redb[w * 128 + tid];
        atomicAdd(&g_nstat[tid], v);
    }
}

// ------------------- kernel 5: fused BN + SiLU + residual -------------------
#define APPLY_NODE_BLOCKS 512
#define APPLY_EDGE_BLOCKS 4096
__global__ void apply_fused(const float* __restrict__ x, const float* __restrict__ ea,
                            const float* __restrict__ vg, const float* __restrict__ vb,
                            const float* __restrict__ eg, const float* __restrict__ eb,
                            float* __restrict__ out) {
    bool isEdge = blockIdx.x >= APPLY_NODE_BLOCKS;
    int bid     = isEdge ? (blockIdx.x - APPLY_NODE_BLOCKS) : blockIdx.x;
    const float* stat  = isEdge ? g_estat : g_nstat;
    float invRows = isEdge ? (1.0f / (float)N_EDGES) : (1.0f / (float)N_NODES);
    const float* gamma = isEdge ? eg : vg;
    const float* beta  = isEdge ? eb : vb;

    int t = bid * blockDim.x + threadIdx.x;
    int c = (t & 15) * 4;
    float A[4], B[4];
    #pragma unroll
    for (int i = 0; i < 4; i++) {
        float m = stat[c + i] * invRows;
        float var = stat[64 + c + i] * invRows - m * m;
        float rs = rsqrtf(var + 1e-5f);
        float gs = gamma[c + i] * rs;
        A[i] = gs;
        B[i] = fmaf(-m, gs, beta[c + i]);
    }
    if (!isEdge) {
        int stride = (APPLY_NODE_BLOCKS * 256) >> 4;
        for (int r = t >> 4; r < N_NODES; r += stride) {
            size_t off = (size_t)r * 64 + c;
            float4 y = __ldcs((const float4*)(g_y + off));
            float4 xv = __ldcs((const float4*)(x + off));
            float z0 = fmaf(y.x, A[0], B[0]);
            float z1 = fmaf(y.y, A[1], B[1]);
            float z2 = fmaf(y.z, A[2], B[2]);
            float z3 = fmaf(y.w, A[3], B[3]);
            float4 o;
            o.x = xv.x + z0 * sigmoidf(z0);
            o.y = xv.y + z1 * sigmoidf(z1);
            o.z = xv.z + z2 * sigmoidf(z2);
            o.w = xv.w + z3 * sigmoidf(z3);
            __stcs((float4*)(out + off), o);
        }
    } else {
        float* ob = out + (size_t)N_NODES * DD;
        int stride = (APPLY_EDGE_BLOCKS * 256) >> 4;
        for (int r = t >> 4; r < N_EDGES; r += stride) {
            size_t off = (size_t)r * 64 + c;
            uint2 u = __ldcs((const uint2*)(g_t + off));
            __half2 h0 = *(__half2*)&u.x;
            __half2 h1 = *(__half2*)&u.y;
            float2 y01 = __half22float2(h0);
            float2 y23 = __half22float2(h1);
            float4 xv = __ldcs((const float4*)(ea + off));
            float z0 = fmaf(y01.x, A[0], B[0]);
            float z1 = fmaf(y01.y, A[1], B[1]);
            float z2 = fmaf(y23.x, A[2], B[2]);
            float z3 = fmaf(y23.y, A[3], B[3]);
            float4 o;
            o.x = xv.x + z0 * sigmoidf(z0);
            o.y = xv.y + z1 * sigmoidf(z1);
            o.z = xv.z + z2 * sigmoidf(z2);
            o.w = xv.w + z3 * sigmoidf(z3);
            __stcs((float4*)(ob + off), o);
        }
    }
}

// ------------------- launch -------------------
extern "C" void kernel_launch(void* const* d_in, const int* in_sizes, int n_in,
                              void* d_out, int out_size) {
    const float* x   = (const float*)d_in[0];
    const float* ea  = (const float*)d_in[1];
    const float* W1  = (const float*)d_in[2];
    const float* b1  = (const float*)d_in[3];
    const float* W2  = (const float*)d_in[4];
    const float* b2  = (const float*)d_in[5];
    const float* W3  = (const float*)d_in[6];
    const float* b3  = (const float*)d_in[7];
    const float* W4  = (const float*)d_in[8];
    const float* b4  = (const float*)d_in[9];
    const float* We  = (const float*)d_in[10];
    const float* be  = (const float*)d_in[11];
    const float* vg  = (const float*)d_in[12];
    const float* vb  = (const float*)d_in[13];
    const float* eg  = (const float*)d_in[14];
    const float* ebt = (const float*)d_in[15];
    const int*   ei  = (const int*)d_in[16];
    const int* srcp = ei;
    const int* dstp = ei + N_EDGES;
    float* out = (float*)d_out;

    cudaFuncSetAttribute(node_gemm, cudaFuncAttributeMaxDynamicSharedMemorySize, NODE_SMEM);
    cudaFuncSetAttribute(edge_pass1, cudaFuncAttributeMaxDynamicSharedMemorySize, EDGE_SMEM);

    prepack<<<16, 256>>>(W1, W2, W3, W4, We, b1, b2, b3, b4);
    node_gemm<<<296, 256, NODE_SMEM>>>(x);
    edge_pass1<<<EDGE_GRID, 256, EDGE_SMEM>>>(ea, srcp, dstp, be);
    node_stats<<<NS_BLOCKS, 256>>>();
    apply_fused<<<APPLY_NODE_BLOCKS + APPLY_EDGE_BLOCKS, 256>>>(x, ea, vg, vb, eg, ebt, out);
}

// round 9
// speedup vs baseline: 1.2381x; 1.2381x over previous
#include <cuda_runtime.h>
#include <cuda_fp16.h>
#include <cstdint>

#define N_NODES 100000
#define N_EDGES 1600000
#define DD 64

typedef unsigned long long u64;

// ------------------- scratch (static device globals; no allocation) -------------------
__device__ float g_x1[(size_t)N_NODES * DD];        // x@W1^T+b1
__device__ float g_x3[(size_t)N_NODES * DD];        // x@W3^T+b3
__device__ float g_x24[(size_t)N_NODES * 2 * DD];   // per node: [x2 row | x4 row]
__device__ float g_y[(size_t)N_NODES * DD];         // x1 + aggregated (pre-BN node)
__device__ float g_sums[(size_t)N_NODES * DD];      // scatter-add accumulator
__device__ float g_cnt[N_NODES];                    // per-src edge counts
__device__ __half g_t[(size_t)N_EDGES * DD];        // pre-BN edge tensor (fp16, 204.8 MB)
__device__ float g_WtN[64 * 256];                   // k-major stacked [W1|W2|W3|W4]
__device__ float g_bN[256];
__device__ float g_WtE[64 * 64];                    // k-major We
__device__ float g_nstat[128];                      // node: sum[64], ssq[64]
__device__ float g_estat[128];                      // edge: sum[64], ssq[64]

// ------------------- helpers -------------------
__device__ __forceinline__ u64 pack2(float lo, float hi) {
    u64 r; unsigned a = __float_as_uint(lo), b = __float_as_uint(hi);
    asm("mov.b64 %0, {%1,%2};" : "=l"(r) : "r"(a), "r"(b));
    return r;
}
__device__ __forceinline__ u64 bcast2(float v) {
    u64 r; unsigned a = __float_as_uint(v);
    asm("mov.b64 %0, {%1,%1};" : "=l"(r) : "r"(a));
    return r;
}
__device__ __forceinline__ void fma2(u64& d, u64 a, u64 b) {
    asm("fma.rn.f32x2 %0, %1, %2, %0;" : "+l"(d) : "l"(a), "l"(b));
}
__device__ __forceinline__ float2 unpack2(u64 v) {
    unsigned lo, hi;
    asm("mov.b64 {%0,%1}, %2;" : "=r"(lo), "=r"(hi) : "l"(v));
    return make_float2(__uint_as_float(lo), __uint_as_float(hi));
}
__device__ __forceinline__ float sigmoidf(float x) { return 1.0f / (1.0f + __expf(-x)); }

__device__ __forceinline__ unsigned sm2u(const void* p) {
    return (unsigned)__cvta_generic_to_shared(p);
}
__device__ __forceinline__ u64 mkpolicy_evict_first() {
    u64 p;
    asm("createpolicy.fractional.L2::evict_first.b64 %0, 1.0;" : "=l"(p));
    return p;
}
__device__ __forceinline__ void cpa16(unsigned s, const void* g) {
    asm volatile("cp.async.cg.shared.global [%0], [%1], 16;" :: "r"(s), "l"(g));
}
__device__ __forceinline__ void cpa16_pol(unsigned s, const void* g, u64 pol) {
    asm volatile("cp.async.cg.shared.global.L2::cache_hint [%0], [%1], 16, %2;"
                 :: "r"(s), "l"(g), "l"(pol));
}
__device__ __forceinline__ void cpa_commit() {
    asm volatile("cp.async.commit_group;");
}
__device__ __forceinline__ void cpa_wait0() {
    asm volatile("cp.async.wait_group 0;");
}
__device__ __forceinline__ void red4(float* p, float a, float b, float c, float d) {
    asm volatile("red.global.add.v4.f32 [%0], {%1,%2,%3,%4};"
                 :: "l"(p), "f"(a), "f"(b), "f"(c), "f"(d) : "memory");
}
__device__ __forceinline__ void st8_cs(__half* p, unsigned a, unsigned b) {
    asm volatile("st.global.cs.v2.b32 [%0], {%1,%2};" :: "l"(p), "r"(a), "r"(b) : "memory");
}

// ------------------- kernel 1: transpose weights to k-major (+ zero stats) -------------------
__global__ void prepack(const float* __restrict__ W1, const float* __restrict__ W2,
                        const float* __restrict__ W3, const float* __restrict__ W4,
                        const float* __restrict__ We, const float* __restrict__ b1,
                        const float* __restrict__ b2, const float* __restrict__ b3,
                        const float* __restrict__ b4) {
    int t = blockIdx.x * blockDim.x + threadIdx.x;
    if (t < 4096) {
        int j = t >> 6, k = t & 63;
        int o = k * 256 + j;
        g_WtN[o]       = W1[t];
        g_WtN[o + 64]  = W2[t];
        g_WtN[o + 128] = W3[t];
        g_WtN[o + 192] = W4[t];
        g_WtE[k * 64 + j] = We[t];
    }
    if (t < 64) {
        g_bN[t] = b1[t]; g_bN[64 + t] = b2[t]; g_bN[128 + t] = b3[t]; g_bN[192 + t] = b4[t];
    }
    if (t < 128) { g_nstat[t] = 0.0f; g_estat[t] = 0.0f; }
}

// ------------------- kernel 2: node GEMMs (x1..x4 fused, f32x2) + zero sums -------------------
#define NODE_SMEM ((16384 + 32 * 68 + 256) * 4)
__global__ __launch_bounds__(256, 2) void node_gemm(const float* __restrict__ x) {
    extern __shared__ float sm[];
    float* WtS = sm;
    float* xs  = sm + 16384;
    float* bS  = sm + 16384 + 2176;
    int tid = threadIdx.x;
    for (int i = tid; i < 16384; i += 256) WtS[i] = g_WtN[i];
    bS[tid] = g_bN[tid];
    __syncthreads();

    int c32 = tid & 31, rg = tid >> 5;
    int j0 = c32 * 4, j1 = 128 + c32 * 4;
    u64 biasv[4] = { pack2(bS[j0], bS[j0 + 1]), pack2(bS[j0 + 2], bS[j0 + 3]),
                     pack2(bS[j1], bS[j1 + 1]), pack2(bS[j1 + 2], bS[j1 + 3]) };

    const float4 z4 = make_float4(0.f, 0.f, 0.f, 0.f);
    const int NT = N_NODES / 32;
    for (int tile = blockIdx.x; tile < NT; tile += gridDim.x) {
        int base = tile * 32;
        const float4* gp = (const float4*)(x + (size_t)base * DD);
        for (int f = tid; f < 512; f += 256) {
            float4 v = gp[f];
            int row = f >> 4, c4 = f & 15;
            *(float4*)&xs[row * 68 + c4 * 4] = v;
            ((float4*)(g_sums + (size_t)base * 64))[f] = z4;
        }
        if (tid < 32) g_cnt[base + tid] = 0.0f;
        __syncthreads();

        u64 acc[4][4];
        #pragma unroll
        for (int rr = 0; rr < 4; rr++) {
            acc[rr][0] = biasv[0]; acc[rr][1] = biasv[1];
            acc[rr][2] = biasv[2]; acc[rr][3] = biasv[3];
        }
        #pragma unroll
        for (int k0 = 0; k0 < 64; k0 += 4) {
            float xr[4][4];
            #pragma unroll
            for (int rr = 0; rr < 4; rr++) {
                float4 a = *(const float4*)&xs[(rg + 8 * rr) * 68 + k0];
                xr[rr][0] = a.x; xr[rr][1] = a.y; xr[rr][2] = a.z; xr[rr][3] = a.w;
            }
            #pragma unroll
            for (int kk = 0; kk < 4; kk++) {
                int k = k0 + kk;
                ulonglong2 wa = *(const ulonglong2*)&WtS[k * 256 + j0];
                ulonglong2 wb = *(const ulonglong2*)&WtS[k * 256 + j1];
                #pragma unroll
                for (int rr = 0; rr < 4; rr++) {
                    u64 av = bcast2(xr[rr][kk]);
                    fma2(acc[rr][0], av, wa.x); fma2(acc[rr][1], av, wa.y);
                    fma2(acc[rr][2], av, wb.x); fma2(acc[rr][3], av, wb.y);
                }
            }
        }
        #pragma unroll
        for (int rr = 0; rr < 4; rr++) {
            int n = base + rg + 8 * rr;
            float2 a0 = unpack2(acc[rr][0]), a1 = unpack2(acc[rr][1]);
            float2 a2 = unpack2(acc[rr][2]), a3 = unpack2(acc[rr][3]);
            float4 vA = make_float4(a0.x, a0.y, a1.x, a1.y);
            float4 vB = make_float4(a2.x, a2.y, a3.x, a3.y);
            float* pA = (c32 < 16) ? &g_x1[(size_t)n * 64 + j0]
                                   : &g_x24[(size_t)n * 128 + (j0 - 64)];
            float* pB = (c32 < 16) ? &g_x3[(size_t)n * 64 + (j1 - 128)]
                                   : &g_x24[(size_t)n * 128 + 64 + (j1 - 192)];
            *(float4*)pA = vA;
            *(float4*)pB = vB;
        }
        __syncthreads();
    }
}

// ------------------- kernel 3: edge pass 1 (128-edge tiles, cp.async pipelined, 1-deep gathers) -------------------
#define W0S_OFF   4096
#define W0S_STRIDE 8704
#define BES_OFF   (4096 + 2 * 8704)
#define IDX_OFF   (BES_OFF + 64)
#define EDGE_SMEM ((IDX_OFF + 512) * 4)
#define ETILES (N_EDGES / 128)

__device__ __forceinline__ void prefetch_tile(float* w0buf, int* sbuf, int* dbuf,
                                              const float* __restrict__ ea,
                                              const int* __restrict__ srcp,
                                              const int* __restrict__ dstp,
                                              int base, int tid, u64 pol) {
    if (tid < 32) {
        cpa16(sm2u(sbuf + tid * 4), srcp + base + tid * 4);
    } else if (tid < 64) {
        int i = tid - 32;
        cpa16(sm2u(dbuf + i * 4), dstp + base + i * 4);
    }
    const float4* gp = (const float4*)(ea + (size_t)base * DD);
    #pragma unroll
    for (int u = 0; u < 8; u++) {
        int f = tid + u * 256;                 // 2048 float4s = full 128x64 tile
        int row = f >> 4, c4 = f & 15;
        cpa16_pol(sm2u(w0buf + row * 68 + c4 * 4), gp + f, pol);
    }
}

__global__ __launch_bounds__(256, 2)
void edge_pass1(const float* __restrict__ ea, const int* __restrict__ srcp,
                const int* __restrict__ dstp, const float* __restrict__ be) {
    extern __shared__ float sm[];
    float* WtS = sm;
    float* beS = sm + BES_OFF;
    int* sS = (int*)(sm + IDX_OFF);
    int* dS = sS + 256;

    int tid = threadIdx.x;
    u64 pol = mkpolicy_evict_first();
    for (int i = tid; i < 4096; i += 256) WtS[i] = g_WtE[i];
    if (tid < 64) beS[tid] = be[tid];

    prefetch_tile(sm + W0S_OFF, sS, dS, ea, srcp, dstp, blockIdx.x * 128, tid, pol);
    cpa_commit();
    __syncthreads();

    int c8 = tid & 7, rq = tid >> 3;
    int j0 = c8 * 4, j1 = 32 + c8 * 4;
    u64 biasv[4] = { pack2(beS[j0], beS[j0 + 1]), pack2(beS[j0 + 2], beS[j0 + 3]),
                     pack2(beS[j1], beS[j1 + 1]), pack2(beS[j1 + 2], beS[j1 + 3]) };

    float ssum[8], sssq[8];
    #pragma unroll
    for (int i = 0; i < 8; i++) { ssum[i] = 0.0f; sssq[i] = 0.0f; }

    int buf = 0;
    for (int tile = blockIdx.x; tile < ETILES; tile += gridDim.x) {
        cpa_wait0();
        __syncthreads();
        float* w0c = sm + W0S_OFF + buf * W0S_STRIDE;
        int* sC = sS + buf * 128;
        int* dC = dS + buf * 128;
        int base = tile * 128;

        // ---- hoist ALL four rows' indices (addresses ready during GEMV) ----
        int sidx[4], didx[4];
        #pragma unroll
        for (int rr = 0; rr < 4; rr++) {
            sidx[rr] = sC[rq + 32 * rr];
            didx[rr] = dC[rq + 32 * rr];
        }

        // ---- early gather for row 0 (hidden under GEMV) ----
        const float* x3p = g_x3 + (size_t)sidx[0] * 64;
        const float* x24p = g_x24 + (size_t)didx[0] * 128;
        float4 p0 = *(const float4*)(x3p + j0);
        float4 p1 = *(const float4*)(x3p + j1);
        float4 p2 = *(const float4*)(x24p + j0);
        float4 p3 = *(const float4*)(x24p + j1);
        float4 p4 = *(const float4*)(x24p + 64 + j0);
        float4 p5 = *(const float4*)(x24p + 64 + j1);

        // ---- issue next tile's prefetch (overlaps GEMV) ----
        int ntile = tile + gridDim.x;
        if (ntile < ETILES)
            prefetch_tile(sm + W0S_OFF + (buf ^ 1) * W0S_STRIDE,
                          sS + (buf ^ 1) * 128, dS + (buf ^ 1) * 128,
                          ea, srcp, dstp, ntile * 128, tid, pol);
        cpa_commit();

        // ---- GEMV: w1 = w0 @ We^T + be ----
        u64 acc[4][4];
        #pragma unroll
        for (int rr = 0; rr < 4; rr++) {
            acc[rr][0] = biasv[0]; acc[rr][1] = biasv[1];
            acc[rr][2] = biasv[2]; acc[rr][3] = biasv[3];
        }
        #pragma unroll
        for (int k0 = 0; k0 < 64; k0 += 4) {
            float w0r[4][4];
            #pragma unroll
            for (int rr = 0; rr < 4; rr++) {
                float4 a = *(const float4*)&w0c[(rq + 32 * rr) * 68 + k0];
                w0r[rr][0] = a.x; w0r[rr][1] = a.y; w0r[rr][2] = a.z; w0r[rr][3] = a.w;
            }
            #pragma unroll
            for (int kk = 0; kk < 4; kk++) {
                int k = k0 + kk;
                ulonglong2 wa = *(const ulonglong2*)&WtS[k * 64 + j0];
                ulonglong2 wb = *(const ulonglong2*)&WtS[k * 64 + j1];
                #pragma unroll
                for (int rr = 0; rr < 4; rr++) {
                    u64 av = bcast2(w0r[rr][kk]);
                    fma2(acc[rr][0], av, wa.x); fma2(acc[rr][1], av, wa.y);
                    fma2(acc[rr][2], av, wb.x); fma2(acc[rr][3], av, wb.y);
                }
            }
        }

        // ---- combine: software-pipelined over the 4 rows (1-deep) ----
        #pragma unroll
        for (int rr = 0; rr < 4; rr++) {
            int row = rq + 32 * rr;
            float4 x3a = p0, x3b = p1, x2a = p2, x2b = p3, x4a = p4, x4b = p5;
            int s_use = sidx[rr];
            if (rr < 3) {
                const float* nx3 = g_x3 + (size_t)sidx[rr + 1] * 64;
                const float* nx24 = g_x24 + (size_t)didx[rr + 1] * 128;
                p0 = *(const float4*)(nx3 + j0);
                p1 = *(const float4*)(nx3 + j1);
                p2 = *(const float4*)(nx24 + j0);
                p3 = *(const float4*)(nx24 + j1);
                p4 = *(const float4*)(nx24 + 64 + j0);
                p5 = *(const float4*)(nx24 + 64 + j1);
            }

            float2 w1_0 = unpack2(acc[rr][0]), w1_1 = unpack2(acc[rr][1]);
            float2 w1_2 = unpack2(acc[rr][2]), w1_3 = unpack2(acc[rr][3]);
            float tv[8];
            tv[0] = w1_0.x + x3a.x + x4a.x;
            tv[1] = w1_0.y + x3a.y + x4a.y;
            tv[2] = w1_1.x + x3a.z + x4a.z;
            tv[3] = w1_1.y + x3a.w + x4a.w;
            tv[4] = w1_2.x + x3b.x + x4b.x;
            tv[5] = w1_2.y + x3b.y + x4b.y;
            tv[6] = w1_3.x + x3b.z + x4b.z;
            tv[7] = w1_3.y + x3b.w + x4b.w;
            size_t eb = (size_t)(base + row) * 64;
            __half2 ha = __floats2half2_rn(tv[0], tv[1]);
            __half2 hb = __floats2half2_rn(tv[2], tv[3]);
            __half2 hc = __floats2half2_rn(tv[4], tv[5]);
            __half2 hd = __floats2half2_rn(tv[6], tv[7]);
            st8_cs(&g_t[eb + j0], *(unsigned*)&ha, *(unsigned*)&hb);
            st8_cs(&g_t[eb + j1], *(unsigned*)&hc, *(unsigned*)&hd);
            #pragma unroll
            for (int i = 0; i < 8; i++) {
                ssum[i] += tv[i];
                sssq[i] = fmaf(tv[i], tv[i], sssq[i]);
            }
            float4 wva = *(const float4*)&w0c[row * 68 + j0];
            float4 wvb = *(const float4*)&w0c[row * 68 + j1];
            float* sp = g_sums + (size_t)s_use * 64;
            red4(sp + j0, sigmoidf(wva.x) * x2a.x, sigmoidf(wva.y) * x2a.y,
                          sigmoidf(wva.z) * x2a.z, sigmoidf(wva.w) * x2a.w);
            red4(sp + j1, sigmoidf(wvb.x) * x2b.x, sigmoidf(wvb.y) * x2b.y,
                          sigmoidf(wvb.z) * x2b.z, sigmoidf(wvb.w) * x2b.w);
            if (c8 == 0) atomicAdd(&g_cnt[s_use], 1.0f);
        }
        buf ^= 1;
    }

    // ---- flush BN stats: warp shfl -> smem block reduction -> 128 atomics/block ----
    #pragma unroll
    for (int i = 0; i < 8; i++) {
        ssum[i] += __shfl_xor_sync(0xffffffffu, ssum[i], 8);
        ssum[i] += __shfl_xor_sync(0xffffffffu, ssum[i], 16);
        sssq[i] += __shfl_xor_sync(0xffffffffu, sssq[i], 8);
        sssq[i] += __shfl_xor_sync(0xffffffffu, sssq[i], 16);
    }
    __syncthreads();               // main loop done in all warps; WtS region now reusable
    float* redb = sm;              // [8 warps][128 stats]
    int warp = tid >> 5, lane = tid & 31;
    if ((lane & 24) == 0) {        // lanes 0..7: hold the 8 col-values for this c8
        #pragma unroll
        for (int i = 0; i < 8; i++) {
            int col = (i < 4) ? (j0 + i) : (j1 + i - 4);
            redb[warp * 128 + col] = ssum[i];
            redb[warp * 128 + 64 + col] = sssq[i];
        }
    }
    __syncthreads();
    if (tid < 128) {
        float v = 0.0f;
        #pragma unroll
        for (int w = 0; w < 8; w++) v += redb[w * 128 + tid];
        atomicAdd(&g_estat[tid], v);
    }
}

// ------------------- kernel 4: node pre-BN + stats (smem-reduced atomics) -------------------
#define NS_BLOCKS 512
__global__ void node_stats() {
    __shared__ float redb[8 * 128];
    int tid = threadIdx.x;
    int t = blockIdx.x * 256 + tid;
    int c = (tid & 15) * 4;
    int stride = (NS_BLOCKS * 256) >> 4;
    float s0 = 0, s1 = 0, s2 = 0, s3 = 0, q0 = 0, q1 = 0, q2 = 0, q3 = 0;
    for (int n = t >> 4; n < N_NODES; n += stride) {
        size_t off = (size_t)n * 64 + c;
        float4 a = *(const float4*)&g_x1[off];
        float4 g = *(const float4*)&g_sums[off];
        float inv = 1.0f / fmaxf(g_cnt[n], 1.0f);
        float4 y;
        y.x = fmaf(g.x, inv, a.x);
        y.y = fmaf(g.y, inv, a.y);
        y.z = fmaf(g.z, inv, a.z);
        y.w = fmaf(g.w, inv, a.w);
        *(float4*)&g_y[off] = y;
        s0 += y.x; q0 = fmaf(y.x, y.x, q0);
        s1 += y.y; q1 = fmaf(y.y, y.y, q1);
        s2 += y.z; q2 = fmaf(y.z, y.z, q2);
        s3 += y.w; q3 = fmaf(y.w, y.w, q3);
    }
    s0 += __shfl_xor_sync(0xffffffffu, s0, 16);
    s1 += __shfl_xor_sync(0xffffffffu, s1, 16);
    s2 += __shfl_xor_sync(0xffffffffu, s2, 16);
    s3 += __shfl_xor_sync(0xffffffffu, s3, 16);
    q0 += __shfl_xor_sync(0xffffffffu, q0, 16);
    q1 += __shfl_xor_sync(0xffffffffu, q1, 16);
    q2 += __shfl_xor_sync(0xffffffffu, q2, 16);
    q3 += __shfl_xor_sync(0xffffffffu, q3, 16);
    int warp = tid >> 5, lane = tid & 31;
    if (lane < 16) {
        redb[warp * 128 + c + 0] = s0;
        redb[warp * 128 + c + 1] = s1;
        redb[warp * 128 + c + 2] = s2;
        redb[warp * 128 + c + 3] = s3;
        redb[warp * 128 + 64 + c + 0] = q0;
        redb[warp * 128 + 64 + c + 1] = q1;
        redb[warp * 128 + 64 + c + 2] = q2;
        redb[warp * 128 + 64 + c + 3] = q3;
    }
    __syncthreads();
    if (tid < 128) {
        float v = 0.0f;
        #pragma unroll
        for (int w = 0; w < 8; w++) v += redb[w * 128 + tid];
        atomicAdd(&g_nstat[tid], v);
    }
}

// ------------------- kernel 5: fused BN + SiLU + residual -------------------
#define APPLY_NODE_BLOCKS 512
#define APPLY_EDGE_BLOCKS 4096
__global__ void apply_fused(const float* __restrict__ x, const float* __restrict__ ea,
                            const float* __restrict__ vg, const float* __restrict__ vb,
                            const float* __restrict__ eg, const float* __restrict__ eb,
                            float* __restrict__ out) {
    bool isEdge = blockIdx.x >= APPLY_NODE_BLOCKS;
    int bid     = isEdge ? (blockIdx.x - APPLY_NODE_BLOCKS) : blockIdx.x;
    const float* stat  = isEdge ? g_estat : g_nstat;
    float invRows = isEdge ? (1.0f / (float)N_EDGES) : (1.0f / (float)N_NODES);
    const float* gamma = isEdge ? eg : vg;
    const float* beta  = isEdge ? eb : vb;

    int t = bid * blockDim.x + threadIdx.x;
    int c = (t & 15) * 4;
    float A[4], B[4];
    #pragma unroll
    for (int i = 0; i < 4; i++) {
        float m = stat[c + i] * invRows;
        float var = stat[64 + c + i] * invRows - m * m;
        float rs = rsqrtf(var + 1e-5f);
        float gs = gamma[c + i] * rs;
        A[i] = gs;
        B[i] = fmaf(-m, gs, beta[c + i]);
    }
    if (!isEdge) {
        int stride = (APPLY_NODE_BLOCKS * 256) >> 4;
        for (int r = t >> 4; r < N_NODES; r += stride) {
            size_t off = (size_t)r * 64 + c;
            float4 y = __ldcs((const float4*)(g_y + off));
            float4 xv = __ldcs((const float4*)(x + off));
            float z0 = fmaf(y.x, A[0], B[0]);
            float z1 = fmaf(y.y, A[1], B[1]);
            float z2 = fmaf(y.z, A[2], B[2]);
            float z3 = fmaf(y.w, A[3], B[3]);
            float4 o;
            o.x = xv.x + z0 * sigmoidf(z0);
            o.y = xv.y + z1 * sigmoidf(z1);
            o.z = xv.z + z2 * sigmoidf(z2);
            o.w = xv.w + z3 * sigmoidf(z3);
            __stcs((float4*)(out + off), o);
        }
    } else {
        float* ob = out + (size_t)N_NODES * DD;
        int stride = (APPLY_EDGE_BLOCKS * 256) >> 4;
        for (int r = t >> 4; r < N_EDGES; r += stride) {
            size_t off = (size_t)r * 64 + c;
            uint2 u = __ldcs((const uint2*)(g_t + off));
            __half2 h0 = *(__half2*)&u.x;
            __half2 h1 = *(__half2*)&u.y;
            float2 y01 = __half22float2(h0);
            float2 y23 = __half22float2(h1);
            float4 xv = __ldcs((const float4*)(ea + off));
            float z0 = fmaf(y01.x, A[0], B[0]);
            float z1 = fmaf(y01.y, A[1], B[1]);
            float z2 = fmaf(y23.x, A[2], B[2]);
            float z3 = fmaf(y23.y, A[3], B[3]);
            float4 o;
            o.x = xv.x + z0 * sigmoidf(z0);
            o.y = xv.y + z1 * sigmoidf(z1);
            o.z = xv.z + z2 * sigmoidf(z2);
            o.w = xv.w + z3 * sigmoidf(z3);
            __stcs((float4*)(ob + off), o);
        }
    }
}

// ------------------- launch -------------------
extern "C" void kernel_launch(void* const* d_in, const int* in_sizes, int n_in,
                              void* d_out, int out_size) {
    const float* x   = (const float*)d_in[0];
    const float* ea  = (const float*)d_in[1];
    const float* W1  = (const float*)d_in[2];
    const float* b1  = (const float*)d_in[3];
    const float* W2  = (const float*)d_in[4];
    const float* b2  = (const float*)d_in[5];
    const float* W3  = (const float*)d_in[6];
    const float* b3  = (const float*)d_in[7];
    const float* W4  = (const float*)d_in[8];
    const float* b4  = (const float*)d_in[9];
    const float* We  = (const float*)d_in[10];
    const float* be  = (const float*)d_in[11];
    const float* vg  = (const float*)d_in[12];
    const float* vb  = (const float*)d_in[13];
    const float* eg  = (const float*)d_in[14];
    const float* ebt = (const float*)d_in[15];
    const int*   ei  = (const int*)d_in[16];
    const int* srcp = ei;
    const int* dstp = ei + N_EDGES;
    float* out = (float*)d_out;

    cudaFuncSetAttribute(node_gemm, cudaFuncAttributeMaxDynamicSharedMemorySize, NODE_SMEM);
    cudaFuncSetAttribute(edge_pass1, cudaFuncAttributeMaxDynamicSharedMemorySize, EDGE_SMEM);

    prepack<<<16, 256>>>(W1, W2, W3, W4, We, b1, b2, b3, b4);
    node_gemm<<<296, 256, NODE_SMEM>>>(x);
    edge_pass1<<<296, 256, EDGE_SMEM>>>(ea, srcp, dstp, be);
    node_stats<<<NS_BLOCKS, 256>>>();
    apply_fused<<<APPLY_NODE_BLOCKS + APPLY_EDGE_BLOCKS, 256>>>(x, ea, vg, vb, eg, ebt, out);
}

// round 10
// speedup vs baseline: 1.4347x; 1.1588x over previous
#include <cuda_runtime.h>
#include <cuda_fp16.h>
#include <cstdint>

#define N_NODES 100000
#define N_EDGES 1600000
#define DD 64

typedef unsigned long long u64;

// ------------------- scratch (static device globals; no allocation) -------------------
__device__ float g_x1[(size_t)N_NODES * DD];        // x@W1^T+b1
__device__ float g_x3[(size_t)N_NODES * DD];        // x@W3^T+b3
__device__ float g_x24[(size_t)N_NODES * 2 * DD];   // per node: [x2 row | x4 row]
__device__ float g_y[(size_t)N_NODES * DD];         // x1 + aggregated (pre-BN node)
__device__ float g_sums[(size_t)N_NODES * DD];      // scatter-add accumulator
__device__ float g_cnt[N_NODES];                    // per-src edge counts
__device__ __half g_t[(size_t)N_EDGES * DD];        // pre-BN edge tensor (fp16, 204.8 MB)
__device__ float g_WtN[64 * 256];                   // k-major stacked [W1|W2|W3|W4]
__device__ float g_bN[256];
__device__ __half g_WeH[64 * 64];                   // We row-major (j*64+k) in fp16
__device__ float g_nstat[128];                      // node: sum[64], ssq[64]
__device__ float g_estat[128];                      // edge: sum[64], ssq[64]

// ------------------- helpers -------------------
__device__ __forceinline__ u64 pack2(float lo, float hi) {
    u64 r; unsigned a = __float_as_uint(lo), b = __float_as_uint(hi);
    asm("mov.b64 %0, {%1,%2};" : "=l"(r) : "r"(a), "r"(b));
    return r;
}
__device__ __forceinline__ u64 bcast2(float v) {
    u64 r; unsigned a = __float_as_uint(v);
    asm("mov.b64 %0, {%1,%1};" : "=l"(r) : "r"(a));
    return r;
}
__device__ __forceinline__ void fma2(u64& d, u64 a, u64 b) {
    asm("fma.rn.f32x2 %0, %1, %2, %0;" : "+l"(d) : "l"(a), "l"(b));
}
__device__ __forceinline__ float2 unpack2(u64 v) {
    unsigned lo, hi;
    asm("mov.b64 {%0,%1}, %2;" : "=r"(lo), "=r"(hi) : "l"(v));
    return make_float2(__uint_as_float(lo), __uint_as_float(hi));
}
__device__ __forceinline__ float sigmoidf(float x) { return 1.0f / (1.0f + __expf(-x)); }

__device__ __forceinline__ unsigned sm2u(const void* p) {
    return (unsigned)__cvta_generic_to_shared(p);
}
__device__ __forceinline__ u64 mkpolicy_evict_first() {
    u64 p;
    asm("createpolicy.fractional.L2::evict_first.b64 %0, 1.0;" : "=l"(p));
    return p;
}
__device__ __forceinline__ void cpa16(unsigned s, const void* g) {
    asm volatile("cp.async.cg.shared.global [%0], [%1], 16;" :: "r"(s), "l"(g));
}
__device__ __forceinline__ void cpa16_pol(unsigned s, const void* g, u64 pol) {
    asm volatile("cp.async.cg.shared.global.L2::cache_hint [%0], [%1], 16, %2;"
                 :: "r"(s), "l"(g), "l"(pol));
}
__device__ __forceinline__ void cpa_commit() {
    asm volatile("cp.async.commit_group;");
}
__device__ __forceinline__ void cpa_wait0() {
    asm volatile("cp.async.wait_group 0;");
}
__device__ __forceinline__ void red4(float* p, float a, float b, float c, float d) {
    asm volatile("red.global.add.v4.f32 [%0], {%1,%2,%3,%4};"
                 :: "l"(p), "f"(a), "f"(b), "f"(c), "f"(d) : "memory");
}
__device__ __forceinline__ void st8_cs(__half* p, unsigned a, unsigned b) {
    asm volatile("st.global.cs.v2.b32 [%0], {%1,%2};" :: "l"(p), "r"(a), "r"(b) : "memory");
}
__device__ __forceinline__ void ldmat4(unsigned& r0, unsigned& r1, unsigned& r2, unsigned& r3,
                                       unsigned addr) {
    asm volatile("ldmatrix.sync.aligned.m8n8.x4.shared.b16 {%0,%1,%2,%3}, [%4];"
                 : "=r"(r0), "=r"(r1), "=r"(r2), "=r"(r3) : "r"(addr));
}
__device__ __forceinline__ void mma16816(float& d0, float& d1, float& d2, float& d3,
                                         unsigned a0, unsigned a1, unsigned a2, unsigned a3,
                                         unsigned b0, unsigned b1) {
    asm volatile("mma.sync.aligned.m16n8k16.row.col.f32.f16.f16.f32 "
                 "{%0,%1,%2,%3},{%4,%5,%6,%7},{%8,%9},{%0,%1,%2,%3};"
                 : "+f"(d0), "+f"(d1), "+f"(d2), "+f"(d3)
                 : "r"(a0), "r"(a1), "r"(a2), "r"(a3), "r"(b0), "r"(b1));
}

// ------------------- kernel 1: prepack weights (+ zero stats) -------------------
__global__ void prepack(const float* __restrict__ W1, const float* __restrict__ W2,
                        const float* __restrict__ W3, const float* __restrict__ W4,
                        const float* __restrict__ We, const float* __restrict__ b1,
                        const float* __restrict__ b2, const float* __restrict__ b3,
                        const float* __restrict__ b4) {
    int t = blockIdx.x * blockDim.x + threadIdx.x;
    if (t < 4096) {
        int j = t >> 6, k = t & 63;
        int o = k * 256 + j;
        g_WtN[o]       = W1[t];
        g_WtN[o + 64]  = W2[t];
        g_WtN[o + 128] = W3[t];
        g_WtN[o + 192] = W4[t];
        g_WeH[t] = __float2half(We[t]);     // keep row-major: [j][k]
    }
    if (t < 64) {
        g_bN[t] = b1[t]; g_bN[64 + t] = b2[t]; g_bN[128 + t] = b3[t]; g_bN[192 + t] = b4[t];
    }
    if (t < 128) { g_nstat[t] = 0.0f; g_estat[t] = 0.0f; }
}

// ------------------- kernel 2: node GEMMs (x1..x4 fused, f32x2) + zero sums -------------------
#define NODE_SMEM ((16384 + 32 * 68 + 256) * 4)
__global__ __launch_bounds__(256, 2) void node_gemm(const float* __restrict__ x) {
    extern __shared__ float sm[];
    float* WtS = sm;
    float* xs  = sm + 16384;
    float* bS  = sm + 16384 + 2176;
    int tid = threadIdx.x;
    for (int i = tid; i < 16384; i += 256) WtS[i] = g_WtN[i];
    bS[tid] = g_bN[tid];
    __syncthreads();

    int c32 = tid & 31, rg = tid >> 5;
    int j0 = c32 * 4, j1 = 128 + c32 * 4;
    u64 biasv[4] = { pack2(bS[j0], bS[j0 + 1]), pack2(bS[j0 + 2], bS[j0 + 3]),
                     pack2(bS[j1], bS[j1 + 1]), pack2(bS[j1 + 2], bS[j1 + 3]) };

    const float4 z4 = make_float4(0.f, 0.f, 0.f, 0.f);
    const int NT = N_NODES / 32;
    for (int tile = blockIdx.x; tile < NT; tile += gridDim.x) {
        int base = tile * 32;
        const float4* gp = (const float4*)(x + (size_t)base * DD);
        for (int f = tid; f < 512; f += 256) {
            float4 v = gp[f];
            int row = f >> 4, c4 = f & 15;
            *(float4*)&xs[row * 68 + c4 * 4] = v;
            ((float4*)(g_sums + (size_t)base * 64))[f] = z4;
        }
        if (tid < 32) g_cnt[base + tid] = 0.0f;
        __syncthreads();

        u64 acc[4][4];
        #pragma unroll
        for (int rr = 0; rr < 4; rr++) {
            acc[rr][0] = biasv[0]; acc[rr][1] = biasv[1];
            acc[rr][2] = biasv[2]; acc[rr][3] = biasv[3];
        }
        #pragma unroll
        for (int k0 = 0; k0 < 64; k0 += 4) {
            float xr[4][4];
            #pragma unroll
            for (int rr = 0; rr < 4; rr++) {
                float4 a = *(const float4*)&xs[(rg + 8 * rr) * 68 + k0];
                xr[rr][0] = a.x; xr[rr][1] = a.y; xr[rr][2] = a.z; xr[rr][3] = a.w;
            }
            #pragma unroll
            for (int kk = 0; kk < 4; kk++) {
                int k = k0 + kk;
                ulonglong2 wa = *(const ulonglong2*)&WtS[k * 256 + j0];
                ulonglong2 wb = *(const ulonglong2*)&WtS[k * 256 + j1];
                #pragma unroll
                for (int rr = 0; rr < 4; rr++) {
                    u64 av = bcast2(xr[rr][kk]);
                    fma2(acc[rr][0], av, wa.x); fma2(acc[rr][1], av, wa.y);
                    fma2(acc[rr][2], av, wb.x); fma2(acc[rr][3], av, wb.y);
                }
            }
        }
        #pragma unroll
        for (int rr = 0; rr < 4; rr++) {
            int n = base + rg + 8 * rr;
            float2 a0 = unpack2(acc[rr][0]), a1 = unpack2(acc[rr][1]);
            float2 a2 = unpack2(acc[rr][2]), a3 = unpack2(acc[rr][3]);
            float4 vA = make_float4(a0.x, a0.y, a1.x, a1.y);
            float4 vB = make_float4(a2.x, a2.y, a3.x, a3.y);
            float* pA = (c32 < 16) ? &g_x1[(size_t)n * 64 + j0]
                                   : &g_x24[(size_t)n * 128 + (j0 - 64)];
            float* pB = (c32 < 16) ? &g_x3[(size_t)n * 64 + (j1 - 128)]
                                   : &g_x24[(size_t)n * 128 + 64 + (j1 - 192)];
            *(float4*)pA = vA;
            *(float4*)pB = vB;
        }
        __syncthreads();
    }
}

// ------------------- kernel 3: edge pass 1 (tensor-core GEMV) -------------------
// smem floats: w1s[128*68] | w0c fp32 [128*68] | w0h fp16 [128*72] | beS[64] | idx 2x(64+64)
#define W1S_OFF 0
#define W0C_OFF 8704
#define W0H_OFF 17408
#define BES_OFF 22016
#define IDX_OFF 22080
#define EDGE_SMEM ((IDX_OFF + 512) * 4)     // 90368 B
#define ETILES (N_EDGES / 128)
#define PITCH32 68
#define PITCH16 72

__device__ __forceinline__ void prefetch_tile(float* w0buf, int* sbuf, int* dbuf,
                                              const float* __restrict__ ea,
                                              const int* __restrict__ srcp,
                                              const int* __restrict__ dstp,
                                              int base, int tid, u64 pol) {
    if (tid < 32) {
        cpa16(sm2u(sbuf + tid * 4), srcp + base + tid * 4);
    } else if (tid < 64) {
        int i = tid - 32;
        cpa16(sm2u(dbuf + i * 4), dstp + base + i * 4);
    }
    const float4* gp = (const float4*)(ea + (size_t)base * DD);
    #pragma unroll
    for (int u = 0; u < 8; u++) {
        int f = tid + u * 256;                 // 2048 float4s = full 128x64 tile
        int row = f >> 4, c4 = f & 15;
        cpa16_pol(sm2u(w0buf + row * PITCH32 + c4 * 4), gp + f, pol);
    }
}

__global__ __launch_bounds__(256, 2)
void edge_pass1(const float* __restrict__ ea, const int* __restrict__ srcp,
                const int* __restrict__ dstp, const float* __restrict__ be) {
    extern __shared__ float sm[];
    float* w1s = sm + W1S_OFF;
    float* w0c = sm + W0C_OFF;
    __half* w0h = (__half*)(sm + W0H_OFF);
    float* beS = sm + BES_OFF;
    int* sS = (int*)(sm + IDX_OFF);        // 2 x 128
    int* dS = sS + 256;                    // 2 x 128

    int tid = threadIdx.x, warp = tid >> 5, lane = tid & 31;
    u64 pol = mkpolicy_evict_first();
    if (tid < 64) beS[tid] = be[tid];

    // ---- per-warp B fragments (n-strip = cols 8*warp..8*warp+7), loop-invariant ----
    unsigned BF[8];
    {
        int g = lane >> 2, t4 = lane & 3;
        int j = warp * 8 + g;
        #pragma unroll
        for (int kt = 0; kt < 4; kt++) {
            BF[kt * 2]     = *(const unsigned*)&g_WeH[j * 64 + kt * 16 + 2 * t4];
            BF[kt * 2 + 1] = *(const unsigned*)&g_WeH[j * 64 + kt * 16 + 8 + 2 * t4];
        }
    }

    prefetch_tile(w0c, sS, dS, ea, srcp, dstp, blockIdx.x * 128, tid, pol);
    cpa_commit();
    __syncthreads();

    float be0, be1;
    { int t4 = lane & 3; be0 = beS[warp * 8 + 2 * t4]; be1 = beS[warp * 8 + 2 * t4 + 1]; }

    int c8 = tid & 7, rq = tid >> 3;
    int j0 = c8 * 4, j1 = 32 + c8 * 4;

    float ssum[8], sssq[8];
    #pragma unroll
    for (int i = 0; i < 8; i++) { ssum[i] = 0.0f; sssq[i] = 0.0f; }

    // ldmatrix lane base: row=(lane&15), col-half=(lane>>4)*8, pitch 72 halves (144 B)
    unsigned ldbase = sm2u(w0h) + (unsigned)(((lane & 15) * PITCH16 + (lane >> 4) * 8) * 2);

    int buf = 0;
    for (int tile = blockIdx.x; tile < ETILES; tile += gridDim.x) {
        cpa_wait0();
        __syncthreads();
        int* sC = sS + buf * 128;
        int* dC = dS + buf * 128;
        int base = tile * 128;

        // ---- hoist indices + issue row-0 gathers (fly during convert+GEMV) ----
        int sidx[4], didx[4];
        #pragma unroll
        for (int rr = 0; rr < 4; rr++) {
            sidx[rr] = sC[rq + 32 * rr];
            didx[rr] = dC[rq + 32 * rr];
        }
        const float* x3p = g_x3 + (size_t)sidx[0] * 64;
        const float* x24p = g_x24 + (size_t)didx[0] * 128;
        float4 p0 = *(const float4*)(x3p + j0);
        float4 p1 = *(const float4*)(x3p + j1);
        float4 p2 = *(const float4*)(x24p + j0);
        float4 p3 = *(const float4*)(x24p + j1);
        float4 p4 = *(const float4*)(x24p + 64 + j0);
        float4 p5 = *(const float4*)(x24p + 64 + j1);

        // ---- convert fp32 tile -> fp16 tile ----
        #pragma unroll
        for (int u = 0; u < 8; u++) {
            int f = tid + u * 256;
            int row = f >> 4, c4 = f & 15;
            float4 v = *(const float4*)&w0c[row * PITCH32 + c4 * 4];
            __half2 h0 = __floats2half2_rn(v.x, v.y);
            __half2 h1 = __floats2half2_rn(v.z, v.w);
            uint2 pk;
            pk.x = *(unsigned*)&h0;
            pk.y = *(unsigned*)&h1;
            *(uint2*)&w0h[row * PITCH16 + c4 * 4] = pk;
        }
        __syncthreads();   // w0h ready; w0c free for next prefetch

        // ---- issue next tile's prefetch (overlaps GEMV + combine) ----
        int ntile = tile + gridDim.x;
        if (ntile < ETILES)
            prefetch_tile(w0c, sS + (buf ^ 1) * 128, dS + (buf ^ 1) * 128,
                          ea, srcp, dstp, ntile * 128, tid, pol);
        cpa_commit();

        // ---- GEMV on tensor pipe: warp w computes cols [8w,8w+8) for all 128 rows ----
        #pragma unroll
        for (int mt = 0; mt < 8; mt++) {
            float d0 = 0.f, d1 = 0.f, d2 = 0.f, d3 = 0.f;
            #pragma unroll
            for (int kt = 0; kt < 4; kt++) {
                unsigned a0, a1, a2, a3;
                ldmat4(a0, a1, a2, a3, ldbase + (unsigned)(mt * 16 * PITCH16 * 2 + kt * 32));
                mma16816(d0, d1, d2, d3, a0, a1, a2, a3, BF[kt * 2], BF[kt * 2 + 1]);
            }
            int r0 = mt * 16 + (lane >> 2);
            int cc = warp * 8 + 2 * (lane & 3);
            *(float2*)&w1s[r0 * PITCH32 + cc] = make_float2(d0 + be0, d1 + be1);
            *(float2*)&w1s[(r0 + 8) * PITCH32 + cc] = make_float2(d2 + be0, d3 + be1);
        }
        __syncthreads();   // w1s visible to all

        // ---- combine: 4 rows, 1-deep pipelined gathers ----
        #pragma unroll
        for (int rr = 0; rr < 4; rr++) {
            int row = rq + 32 * rr;
            float4 x3a = p0, x3b = p1, x2a = p2, x2b = p3, x4a = p4, x4b = p5;
            int s_use = sidx[rr];
            if (rr < 3) {
                const float* nx3 = g_x3 + (size_t)sidx[rr + 1] * 64;
                const float* nx24 = g_x24 + (size_t)didx[rr + 1] * 128;
                p0 = *(const float4*)(nx3 + j0);
                p1 = *(const float4*)(nx3 + j1);
                p2 = *(const float4*)(nx24 + j0);
                p3 = *(const float4*)(nx24 + j1);
                p4 = *(const float4*)(nx24 + 64 + j0);
                p5 = *(const float4*)(nx24 + 64 + j1);
            }

            float2 w1_0 = *(const float2*)&w1s[row * PITCH32 + j0];
            float2 w1_1 = *(const float2*)&w1s[row * PITCH32 + j0 + 2];
            float2 w1_2 = *(const float2*)&w1s[row * PITCH32 + j1];
            float2 w1_3 = *(const float2*)&w1s[row * PITCH32 + j1 + 2];
            float tv[8];
            tv[0] = w1_0.x + x3a.x + x4a.x;
            tv[1] = w1_0.y + x3a.y + x4a.y;
            tv[2] = w1_1.x + x3a.z + x4a.z;
            tv[3] = w1_1.y + x3a.w + x4a.w;
            tv[4] = w1_2.x + x3b.x + x4b.x;
            tv[5] = w1_2.y + x3b.y + x4b.y;
            tv[6] = w1_3.x + x3b.z + x4b.z;
            tv[7] = w1_3.y + x3b.w + x4b.w;
            size_t eb = (size_t)(base + row) * 64;
            __half2 ha = __floats2half2_rn(tv[0], tv[1]);
            __half2 hb = __floats2half2_rn(tv[2], tv[3]);
            __half2 hc = __floats2half2_rn(tv[4], tv[5]);
            __half2 hd = __floats2half2_rn(tv[6], tv[7]);
            st8_cs(&g_t[eb + j0], *(unsigned*)&ha, *(unsigned*)&hb);
            st8_cs(&g_t[eb + j1], *(unsigned*)&hc, *(unsigned*)&hd);
            #pragma unroll
            for (int i = 0; i < 8; i++) {
                ssum[i] += tv[i];
                sssq[i] = fmaf(tv[i], tv[i], sssq[i]);
            }
            // sigmoid gate from fp16 w0
            float2 wa01 = __half22float2(*(const __half2*)&w0h[row * PITCH16 + j0]);
            float2 wa23 = __half22float2(*(const __half2*)&w0h[row * PITCH16 + j0 + 2]);
            float2 wb01 = __half22float2(*(const __half2*)&w0h[row * PITCH16 + j1]);
            float2 wb23 = __half22float2(*(const __half2*)&w0h[row * PITCH16 + j1 + 2]);
            float* sp = g_sums + (size_t)s_use * 64;
            red4(sp + j0, sigmoidf(wa01.x) * x2a.x, sigmoidf(wa01.y) * x2a.y,
                          sigmoidf(wa23.x) * x2a.z, sigmoidf(wa23.y) * x2a.w);
            red4(sp + j1, sigmoidf(wb01.x) * x2b.x, sigmoidf(wb01.y) * x2b.y,
                          sigmoidf(wb23.x) * x2b.z, sigmoidf(wb23.y) * x2b.w);
            if (c8 == 0) atomicAdd(&g_cnt[s_use], 1.0f);
        }
        buf ^= 1;
    }

    // ---- flush BN stats: warp shfl -> smem block reduction -> 128 atomics/block ----
    #pragma unroll
    for (int i = 0; i < 8; i++) {
        ssum[i] += __shfl_xor_sync(0xffffffffu, ssum[i], 8);
        ssum[i] += __shfl_xor_sync(0xffffffffu, ssum[i], 16);
        sssq[i] += __shfl_xor_sync(0xffffffffu, sssq[i], 8);
        sssq[i] += __shfl_xor_sync(0xffffffffu, sssq[i], 16);
    }
    __syncthreads();
    float* redb = sm;              // reuse w1s region: [8 warps][128 stats]
    if ((lane & 24) == 0) {
        #pragma unroll
        for (int i = 0; i < 8; i++) {
            int col = (i < 4) ? (j0 + i) : (j1 + i - 4);
            redb[warp * 128 + col] = ssum[i];
            redb[warp * 128 + 64 + col] = sssq[i];
        }
    }
    __syncthreads();
    if (tid < 128) {
        float v = 0.0f;
        #pragma unroll
        for (int w = 0; w < 8; w++) v += redb[w * 128 + tid];
        atomicAdd(&g_estat[tid], v);
    }
}

// ------------------- kernel 4: node pre-BN + stats (smem-reduced atomics) -------------------
#define NS_BLOCKS 512
__global__ void node_stats() {
    __shared__ float redb[8 * 128];
    int tid = threadIdx.x;
    int t = blockIdx.x * 256 + tid;
    int c = (tid & 15) * 4;
    int stride = (NS_BLOCKS * 256) >> 4;
    float s0 = 0, s1 = 0, s2 = 0, s3 = 0, q0 = 0, q1 = 0, q2 = 0, q3 = 0;
    for (int n = t >> 4; n < N_NODES; n += stride) {
        size_t off = (size_t)n * 64 + c;
        float4 a = *(const float4*)&g_x1[off];
        float4 g = *(const float4*)&g_sums[off];
        float inv = 1.0f / fmaxf(g_cnt[n], 1.0f);
        float4 y;
        y.x = fmaf(g.x, inv, a.x);
        y.y = fmaf(g.y, inv, a.y);
        y.z = fmaf(g.z, inv, a.z);
        y.w = fmaf(g.w, inv, a.w);
        *(float4*)&g_y[off] = y;
        s0 += y.x; q0 = fmaf(y.x, y.x, q0);
        s1 += y.y; q1 = fmaf(y.y, y.y, q1);
        s2 += y.z; q2 = fmaf(y.z, y.z, q2);
        s3 += y.w; q3 = fmaf(y.w, y.w, q3);
    }
    s0 += __shfl_xor_sync(0xffffffffu, s0, 16);
    s1 += __shfl_xor_sync(0xffffffffu, s1, 16);
    s2 += __shfl_xor_sync(0xffffffffu, s2, 16);
    s3 += __shfl_xor_sync(0xffffffffu, s3, 16);
    q0 += __shfl_xor_sync(0xffffffffu, q0, 16);
    q1 += __shfl_xor_sync(0xffffffffu, q1, 16);
    q2 += __shfl_xor_sync(0xffffffffu, q2, 16);
    q3 += __shfl_xor_sync(0xffffffffu, q3, 16);
    int warp = tid >> 5, lane = tid & 31;
    if (lane < 16) {
        redb[warp * 128 + c + 0] = s0;
        redb[warp * 128 + c + 1] = s1;
        redb[warp * 128 + c + 2] = s2;
        redb[warp * 128 + c + 3] = s3;
        redb[warp * 128 + 64 + c + 0] = q0;
        redb[warp * 128 + 64 + c + 1] = q1;
        redb[warp * 128 + 64 + c + 2] = q2;
        redb[warp * 128 + 64 + c + 3] = q3;
    }
    __syncthreads();
    if (tid < 128) {
        float v = 0.0f;
        #pragma unroll
        for (int w = 0; w < 8; w++) v += redb[w * 128 + tid];
        atomicAdd(&g_nstat[tid], v);
    }
}

// ------------------- kernel 5: fused BN + SiLU + residual -------------------
#define APPLY_NODE_BLOCKS 512
#define APPLY_EDGE_BLOCKS 4096
__global__ void apply_fused(const float* __restrict__ x, const float* __restrict__ ea,
                            const float* __restrict__ vg, const float* __restrict__ vb,
                            const float* __restrict__ eg, const float* __restrict__ eb,
                            float* __restrict__ out) {
    bool isEdge = blockIdx.x >= APPLY_NODE_BLOCKS;
    int bid     = isEdge ? (blockIdx.x - APPLY_NODE_BLOCKS) : blockIdx.x;
    const float* stat  = isEdge ? g_estat : g_nstat;
    float invRows = isEdge ? (1.0f / (float)N_EDGES) : (1.0f / (float)N_NODES);
    const float* gamma = isEdge ? eg : vg;
    const float* beta  = isEdge ? eb : vb;

    int t = bid * blockDim.x + threadIdx.x;
    int c = (t & 15) * 4;
    float A[4], B[4];
    #pragma unroll
    for (int i = 0; i < 4; i++) {
        float m = stat[c + i] * invRows;
        float var = stat[64 + c + i] * invRows - m * m;
        float rs = rsqrtf(var + 1e-5f);
        float gs = gamma[c + i] * rs;
        A[i] = gs;
        B[i] = fmaf(-m, gs, beta[c + i]);
    }
    if (!isEdge) {
        int stride = (APPLY_NODE_BLOCKS * 256) >> 4;
        for (int r = t >> 4; r < N_NODES; r += stride) {
            size_t off = (size_t)r * 64 + c;
            float4 y = __ldcs((const float4*)(g_y + off));
            float4 xv = __ldcs((const float4*)(x + off));
            float z0 = fmaf(y.x, A[0], B[0]);
            float z1 = fmaf(y.y, A[1], B[1]);
            float z2 = fmaf(y.z, A[2], B[2]);
            float z3 = fmaf(y.w, A[3], B[3]);
            float4 o;
            o.x = xv.x + z0 * sigmoidf(z0);
            o.y = xv.y + z1 * sigmoidf(z1);
            o.z = xv.z + z2 * sigmoidf(z2);
            o.w = xv.w + z3 * sigmoidf(z3);
            __stcs((float4*)(out + off), o);
        }
    } else {
        float* ob = out + (size_t)N_NODES * DD;
        int stride = (APPLY_EDGE_BLOCKS * 256) >> 4;
        for (int r = t >> 4; r < N_EDGES; r += stride) {
            size_t off = (size_t)r * 64 + c;
            uint2 u = __ldcs((const uint2*)(g_t + off));
            __half2 h0 = *(__half2*)&u.x;
            __half2 h1 = *(__half2*)&u.y;
            float2 y01 = __half22float2(h0);
            float2 y23 = __half22float2(h1);
            float4 xv = __ldcs((const float4*)(ea + off));
            float z0 = fmaf(y01.x, A[0], B[0]);
            float z1 = fmaf(y01.y, A[1], B[1]);
            float z2 = fmaf(y23.x, A[2], B[2]);
            float z3 = fmaf(y23.y, A[3], B[3]);
            float4 o;
            o.x = xv.x + z0 * sigmoidf(z0);
            o.y = xv.y + z1 * sigmoidf(z1);
            o.z = xv.z + z2 * sigmoidf(z2);
            o.w = xv.w + z3 * sigmoidf(z3);
            __stcs((float4*)(ob + off), o);
        }
    }
}

// ------------------- launch -------------------
extern "C" void kernel_launch(void* const* d_in, const int* in_sizes, int n_in,
                              void* d_out, int out_size) {
    const float* x   = (const float*)d_in[0];
    const float* ea  = (const float*)d_in[1];
    const float* W1  = (const float*)d_in[2];
    const float* b1  = (const float*)d_in[3];
    const float* W2  = (const float*)d_in[4];
    const float* b2  = (const float*)d_in[5];
    const float* W3  = (const float*)d_in[6];
    const float* b3  = (const float*)d_in[7];
    const float* W4  = (const float*)d_in[8];
    const float* b4  = (const float*)d_in[9];
    const float* We  = (const float*)d_in[10];
    const float* be  = (const float*)d_in[11];
    const float* vg  = (const float*)d_in[12];
    const float* vb  = (const float*)d_in[13];
    const float* eg  = (const float*)d_in[14];
    const float* ebt = (const float*)d_in[15];
    const int*   ei  = (const int*)d_in[16];
    const int* srcp = ei;
    const int* dstp = ei + N_EDGES;
    float* out = (float*)d_out;

    cudaFuncSetAttribute(node_gemm, cudaFuncAttributeMaxDynamicSharedMemorySize, NODE_SMEM);
    cudaFuncSetAttribute(edge_pass1, cudaFuncAttributeMaxDynamicSharedMemorySize, EDGE_SMEM);

    prepack<<<16, 256>>>(W1, W2, W3, W4, We, b1, b2, b3, b4);
    node_gemm<<<296, 256, NODE_SMEM>>>(x);
    edge_pass1<<<296, 256, EDGE_SMEM>>>(ea, srcp, dstp, be);
    node_stats<<<NS_BLOCKS, 256>>>();
    apply_fused<<<APPLY_NODE_BLOCKS + APPLY_EDGE_BLOCKS, 256>>>(x, ea, vg, vb, eg, ebt, out);
}

// round 11
// speedup vs baseline: 1.5703x; 1.0945x over previous
#include <cuda_runtime.h>
#include <cuda_fp16.h>
#include <cstdint>

#define N_NODES 100000
#define N_EDGES 1600000
#define DD 64

typedef unsigned long long u64;

// ------------------- scratch (static device globals; no allocation) -------------------
__device__ float g_x1[(size_t)N_NODES * DD];        // x@W1^T+b1
__device__ float g_x3[(size_t)N_NODES * DD];        // x@W3^T+b3
__device__ float g_x24[(size_t)N_NODES * 2 * DD];   // per node: [x2 row | x4 row]
__device__ float g_y[(size_t)N_NODES * DD];         // x1 + aggregated (pre-BN node)
__device__ float g_sums[(size_t)N_NODES * DD];      // scatter-add accumulator
__device__ float g_cnt[N_NODES];                    // per-src edge counts
__device__ __half g_t[(size_t)N_EDGES * DD];        // pre-BN edge tensor (fp16, 204.8 MB)
__device__ float g_bN[256];
__device__ __half g_WNH[256 * 64];                  // stacked [W1;W2;W3;W4] row-major fp16
__device__ __half g_WeH[64 * 64];                   // We row-major (j*64+k) in fp16
__device__ float g_nstat[128];                      // node: sum[64], ssq[64]
__device__ float g_estat[128];                      // edge: sum[64], ssq[64]

// ------------------- helpers -------------------
__device__ __forceinline__ float sigmoidf(float x) { return 1.0f / (1.0f + __expf(-x)); }

__device__ __forceinline__ unsigned sm2u(const void* p) {
    return (unsigned)__cvta_generic_to_shared(p);
}
__device__ __forceinline__ u64 mkpolicy_evict_first() {
    u64 p;
    asm("createpolicy.fractional.L2::evict_first.b64 %0, 1.0;" : "=l"(p));
    return p;
}
__device__ __forceinline__ void cpa16(unsigned s, const void* g) {
    asm volatile("cp.async.cg.shared.global [%0], [%1], 16;" :: "r"(s), "l"(g));
}
__device__ __forceinline__ void cpa16_pol(unsigned s, const void* g, u64 pol) {
    asm volatile("cp.async.cg.shared.global.L2::cache_hint [%0], [%1], 16, %2;"
                 :: "r"(s), "l"(g), "l"(pol));
}
__device__ __forceinline__ void cpa_commit() {
    asm volatile("cp.async.commit_group;");
}
__device__ __forceinline__ void cpa_wait0() {
    asm volatile("cp.async.wait_group 0;");
}
__device__ __forceinline__ void red4(float* p, float a, float b, float c, float d) {
    asm volatile("red.global.add.v4.f32 [%0], {%1,%2,%3,%4};"
                 :: "l"(p), "f"(a), "f"(b), "f"(c), "f"(d) : "memory");
}
__device__ __forceinline__ void st8_cs(__half* p, unsigned a, unsigned b) {
    asm volatile("st.global.cs.v2.b32 [%0], {%1,%2};" :: "l"(p), "r"(a), "r"(b) : "memory");
}
__device__ __forceinline__ void ldmat4(unsigned& r0, unsigned& r1, unsigned& r2, unsigned& r3,
                                       unsigned addr) {
    asm volatile("ldmatrix.sync.aligned.m8n8.x4.shared.b16 {%0,%1,%2,%3}, [%4];"
                 : "=r"(r0), "=r"(r1), "=r"(r2), "=r"(r3) : "r"(addr));
}
__device__ __forceinline__ void mma16816(float& d0, float& d1, float& d2, float& d3,
                                         unsigned a0, unsigned a1, unsigned a2, unsigned a3,
                                         unsigned b0, unsigned b1) {
    asm volatile("mma.sync.aligned.m16n8k16.row.col.f32.f16.f16.f32 "
                 "{%0,%1,%2,%3},{%4,%5,%6,%7},{%8,%9},{%0,%1,%2,%3};"
                 : "+f"(d0), "+f"(d1), "+f"(d2), "+f"(d3)
                 : "r"(a0), "r"(a1), "r"(a2), "r"(a3), "r"(b0), "r"(b1));
}

// ------------------- kernel 1: prepack weights (+ zero stats) -------------------
__global__ void prepack(const float* __restrict__ W1, const float* __restrict__ W2,
                        const float* __restrict__ W3, const float* __restrict__ W4,
                        const float* __restrict__ We, const float* __restrict__ b1,
                        const float* __restrict__ b2, const float* __restrict__ b3,
                        const float* __restrict__ b4) {
    int t = blockIdx.x * blockDim.x + threadIdx.x;
    if (t < 4096) {
        g_WNH[t]            = __float2half(W1[t]);   // rows 0..63
        g_WNH[4096 + t]     = __float2half(W2[t]);   // rows 64..127
        g_WNH[8192 + t]     = __float2half(W3[t]);   // rows 128..191
        g_WNH[12288 + t]    = __float2half(W4[t]);   // rows 192..255
        g_WeH[t] = __float2half(We[t]);              // row-major [j][k]
    }
    if (t < 64) {
        g_bN[t] = b1[t]; g_bN[64 + t] = b2[t]; g_bN[128 + t] = b3[t]; g_bN[192 + t] = b4[t];
    }
    if (t < 128) { g_nstat[t] = 0.0f; g_estat[t] = 0.0f; }
}

// ------------------- kernel 2: node GEMMs on tensor pipe (x1,x2,x3,x4 fused) -------------------
// tile = 128 nodes. A = x tile fp16 [128][72-pitch]; B = g_WNH strip per warp (32 cols).
#define NPITCH16 72
#define NODE_TILES ((N_NODES + 127) / 128)
__global__ __launch_bounds__(256, 2) void node_gemm(const float* __restrict__ x) {
    __shared__ __align__(16) __half xh[128 * NPITCH16];
    int tid = threadIdx.x, warp = tid >> 5, lane = tid & 31;
    int t4 = lane & 3;

    // ---- loop-invariant B fragments: 4 n8 groups of this warp's 32-col strip ----
    unsigned BF[32];
    float bb0[4], bb1[4];
    float* gbase[4];
    size_t gstride[4];
    #pragma unroll
    for (int g = 0; g < 4; g++) {
        int j = warp * 32 + g * 8 + (lane >> 2);     // B row (output col) for ldmatrix-less frag
        #pragma unroll
        for (int kt = 0; kt < 4; kt++) {
            BF[g * 8 + kt * 2]     = *(const unsigned*)&g_WNH[j * 64 + kt * 16 + 2 * t4];
            BF[g * 8 + kt * 2 + 1] = *(const unsigned*)&g_WNH[j * 64 + kt * 16 + 8 + 2 * t4];
        }
        int jc = warp * 32 + g * 8 + 2 * t4;         // this thread's output column
        bb0[g] = g_bN[jc]; bb1[g] = g_bN[jc + 1];
        if (jc < 64)       { gbase[g] = g_x1 + jc;              gstride[g] = 64;  }
        else if (jc < 128) { gbase[g] = g_x24 + (jc - 64);      gstride[g] = 128; }
        else if (jc < 192) { gbase[g] = g_x3 + (jc - 128);      gstride[g] = 64;  }
        else               { gbase[g] = g_x24 + 64 + (jc - 192); gstride[g] = 128; }
    }

    unsigned ldbase = sm2u(xh) + (unsigned)(((lane & 15) * NPITCH16 + (lane >> 4) * 8) * 2);
    const float4 z4 = make_float4(0.f, 0.f, 0.f, 0.f);

    for (int tile = blockIdx.x; tile < NODE_TILES; tile += gridDim.x) {
        int base = tile * 128;
        // ---- load x tile -> fp16 smem; zero g_sums/g_cnt for these nodes ----
        for (int f = tid; f < 2048; f += 256) {
            int row = f >> 4, c4 = f & 15;
            int n = base + row;
            float4 v = z4;
            if (n < N_NODES) {
                v = ((const float4*)(x + (size_t)n * 64))[c4];
                ((float4*)(g_sums + (size_t)n * 64))[c4] = z4;
            }
            __half2 h0 = __floats2half2_rn(v.x, v.y);
            __half2 h1 = __floats2half2_rn(v.z, v.w);
            uint2 pk;
            pk.x = *(unsigned*)&h0;
            pk.y = *(unsigned*)&h1;
            *(uint2*)&xh[row * NPITCH16 + c4 * 4] = pk;
        }
        if (tid < 128 && base + tid < N_NODES) g_cnt[base + tid] = 0.0f;
        __syncthreads();

        #pragma unroll
        for (int mt = 0; mt < 8; mt++) {
            unsigned A[16];
            #pragma unroll
            for (int kt = 0; kt < 4; kt++)
                ldmat4(A[kt * 4], A[kt * 4 + 1], A[kt * 4 + 2], A[kt * 4 + 3],
                       ldbase + (unsigned)(mt * 16 * NPITCH16 * 2 + kt * 32));
            int r0 = mt * 16 + (lane >> 2);
            int n0 = base + r0, n1 = n0 + 8;
            #pragma unroll
            for (int g = 0; g < 4; g++) {
                float d0 = 0.f, d1 = 0.f, d2 = 0.f, d3 = 0.f;
                #pragma unroll
                for (int kt = 0; kt < 4; kt++)
                    mma16816(d0, d1, d2, d3, A[kt * 4], A[kt * 4 + 1], A[kt * 4 + 2], A[kt * 4 + 3],
                             BF[g * 8 + kt * 2], BF[g * 8 + kt * 2 + 1]);
                if (n0 < N_NODES)
                    *(float2*)(gbase[g] + (size_t)n0 * gstride[g]) = make_float2(d0 + bb0[g], d1 + bb1[g]);
                if (n1 < N_NODES)
                    *(float2*)(gbase[g] + (size_t)n1 * gstride[g]) = make_float2(d2 + bb0[g], d3 + bb1[g]);
            }
        }
        __syncthreads();
    }
}

// ------------------- kernel 3: edge pass 1 (tensor-core GEMV) -------------------
// smem floats: w1s[128*68] | w0c fp32 [128*68] | w0h fp16 [128*72] | beS[64] | idx 2x(64+64)
#define W1S_OFF 0
#define W0C_OFF 8704
#define W0H_OFF 17408
#define BES_OFF 22016
#define IDX_OFF 22080
#define EDGE_SMEM ((IDX_OFF + 512) * 4)     // 90368 B
#define ETILES (N_EDGES / 128)
#define PITCH32 68
#define PITCH16 72

__device__ __forceinline__ void prefetch_tile(float* w0buf, int* sbuf, int* dbuf,
                                              const float* __restrict__ ea,
                                              const int* __restrict__ srcp,
                                              const int* __restrict__ dstp,
                                              int base, int tid, u64 pol) {
    if (tid < 32) {
        cpa16(sm2u(sbuf + tid * 4), srcp + base + tid * 4);
    } else if (tid < 64) {
        int i = tid - 32;
        cpa16(sm2u(dbuf + i * 4), dstp + base + i * 4);
    }
    const float4* gp = (const float4*)(ea + (size_t)base * DD);
    #pragma unroll
    for (int u = 0; u < 8; u++) {
        int f = tid + u * 256;                 // 2048 float4s = full 128x64 tile
        int row = f >> 4, c4 = f & 15;
        cpa16_pol(sm2u(w0buf + row * PITCH32 + c4 * 4), gp + f, pol);
    }
}

__global__ __launch_bounds__(256, 2)
void edge_pass1(const float* __restrict__ ea, const int* __restrict__ srcp,
                const int* __restrict__ dstp, const float* __restrict__ be) {
    extern __shared__ float sm[];
    float* w1s = sm + W1S_OFF;
    float* w0c = sm + W0C_OFF;
    __half* w0h = (__half*)(sm + W0H_OFF);
    float* beS = sm + BES_OFF;
    int* sS = (int*)(sm + IDX_OFF);        // 2 x 128
    int* dS = sS + 256;                    // 2 x 128

    int tid = threadIdx.x, warp = tid >> 5, lane = tid & 31;
    u64 pol = mkpolicy_evict_first();
    if (tid < 64) beS[tid] = be[tid];

    // ---- per-warp B fragments (n-strip = cols 8*warp..8*warp+7), loop-invariant ----
    unsigned BF[8];
    {
        int g = lane >> 2, t4 = lane & 3;
        int j = warp * 8 + g;
        #pragma unroll
        for (int kt = 0; kt < 4; kt++) {
            BF[kt * 2]     = *(const unsigned*)&g_WeH[j * 64 + kt * 16 + 2 * t4];
            BF[kt * 2 + 1] = *(const unsigned*)&g_WeH[j * 64 + kt * 16 + 8 + 2 * t4];
        }
    }

    prefetch_tile(w0c, sS, dS, ea, srcp, dstp, blockIdx.x * 128, tid, pol);
    cpa_commit();
    __syncthreads();

    float be0, be1;
    { int t4 = lane & 3; be0 = beS[warp * 8 + 2 * t4]; be1 = beS[warp * 8 + 2 * t4 + 1]; }

    int c8 = tid & 7, rq = tid >> 3;
    int j0 = c8 * 4, j1 = 32 + c8 * 4;

    float ssum[8], sssq[8];
    #pragma unroll
    for (int i = 0; i < 8; i++) { ssum[i] = 0.0f; sssq[i] = 0.0f; }

    // ldmatrix lane base: row=(lane&15), col-half=(lane>>4)*8, pitch 72 halves (144 B)
    unsigned ldbase = sm2u(w0h) + (unsigned)(((lane & 15) * PITCH16 + (lane >> 4) * 8) * 2);

    int buf = 0;
    for (int tile = blockIdx.x; tile < ETILES; tile += gridDim.x) {
        cpa_wait0();
        __syncthreads();
        int* sC = sS + buf * 128;
        int* dC = dS + buf * 128;
        int base = tile * 128;

        // ---- hoist indices + issue row-0 gathers (fly during convert+GEMV) ----
        int sidx[4], didx[4];
        #pragma unroll
        for (int rr = 0; rr < 4; rr++) {
            sidx[rr] = sC[rq + 32 * rr];
            didx[rr] = dC[rq + 32 * rr];
        }
        const float* x3p = g_x3 + (size_t)sidx[0] * 64;
        const float* x24p = g_x24 + (size_t)didx[0] * 128;
        float4 p0 = *(const float4*)(x3p + j0);
        float4 p1 = *(const float4*)(x3p + j1);
        float4 p2 = *(const float4*)(x24p + j0);
        float4 p3 = *(const float4*)(x24p + j1);
        float4 p4 = *(const float4*)(x24p + 64 + j0);
        float4 p5 = *(const float4*)(x24p + 64 + j1);

        // ---- convert fp32 tile -> fp16 tile ----
        #pragma unroll
        for (int u = 0; u < 8; u++) {
            int f = tid + u * 256;
            int row = f >> 4, c4 = f & 15;
            float4 v = *(const float4*)&w0c[row * PITCH32 + c4 * 4];
            __half2 h0 = __floats2half2_rn(v.x, v.y);
            __half2 h1 = __floats2half2_rn(v.z, v.w);
            uint2 pk;
            pk.x = *(unsigned*)&h0;
            pk.y = *(unsigned*)&h1;
            *(uint2*)&w0h[row * PITCH16 + c4 * 4] = pk;
        }
        __syncthreads();   // w0h ready; w0c free for next prefetch

        // ---- issue next tile's prefetch (overlaps GEMV + combine) ----
        int ntile = tile + gridDim.x;
        if (ntile < ETILES)
            prefetch_tile(w0c, sS + (buf ^ 1) * 128, dS + (buf ^ 1) * 128,
                          ea, srcp, dstp, ntile * 128, tid, pol);
        cpa_commit();

        // ---- GEMV on tensor pipe: warp w computes cols [8w,8w+8) for all 128 rows ----
        #pragma unroll
        for (int mt = 0; mt < 8; mt++) {
            float d0 = 0.f, d1 = 0.f, d2 = 0.f, d3 = 0.f;
            #pragma unroll
            for (int kt = 0; kt < 4; kt++) {
                unsigned a0, a1, a2, a3;
                ldmat4(a0, a1, a2, a3, ldbase + (unsigned)(mt * 16 * PITCH16 * 2 + kt * 32));
                mma16816(d0, d1, d2, d3, a0, a1, a2, a3, BF[kt * 2], BF[kt * 2 + 1]);
            }
            int r0 = mt * 16 + (lane >> 2);
            int cc = warp * 8 + 2 * (lane & 3);
            *(float2*)&w1s[r0 * PITCH32 + cc] = make_float2(d0 + be0, d1 + be1);
            *(float2*)&w1s[(r0 + 8) * PITCH32 + cc] = make_float2(d2 + be0, d3 + be1);
        }
        __syncthreads();   // w1s visible to all

        // ---- combine: 4 rows, 1-deep pipelined gathers ----
        #pragma unroll
        for (int rr = 0; rr < 4; rr++) {
            int row = rq + 32 * rr;
            float4 x3a = p0, x3b = p1, x2a = p2, x2b = p3, x4a = p4, x4b = p5;
            int s_use = sidx[rr];
            if (rr < 3) {
                const float* nx3 = g_x3 + (size_t)sidx[rr + 1] * 64;
                const float* nx24 = g_x24 + (size_t)didx[rr + 1] * 128;
                p0 = *(const float4*)(nx3 + j0);
                p1 = *(const float4*)(nx3 + j1);
                p2 = *(const float4*)(nx24 + j0);
                p3 = *(const float4*)(nx24 + j1);
                p4 = *(const float4*)(nx24 + 64 + j0);
                p5 = *(const float4*)(nx24 + 64 + j1);
            }

            float2 w1_0 = *(const float2*)&w1s[row * PITCH32 + j0];
            float2 w1_1 = *(const float2*)&w1s[row * PITCH32 + j0 + 2];
            float2 w1_2 = *(const float2*)&w1s[row * PITCH32 + j1];
            float2 w1_3 = *(const float2*)&w1s[row * PITCH32 + j1 + 2];
            float tv[8];
            tv[0] = w1_0.x + x3a.x + x4a.x;
            tv[1] = w1_0.y + x3a.y + x4a.y;
            tv[2] = w1_1.x + x3a.z + x4a.z;
            tv[3] = w1_1.y + x3a.w + x4a.w;
            tv[4] = w1_2.x + x3b.x + x4b.x;
            tv[5] = w1_2.y + x3b.y + x4b.y;
            tv[6] = w1_3.x + x3b.z + x4b.z;
            tv[7] = w1_3.y + x3b.w + x4b.w;
            size_t eb = (size_t)(base + row) * 64;
            __half2 ha = __floats2half2_rn(tv[0], tv[1]);
            __half2 hb = __floats2half2_rn(tv[2], tv[3]);
            __half2 hc = __floats2half2_rn(tv[4], tv[5]);
            __half2 hd = __floats2half2_rn(tv[6], tv[7]);
            st8_cs(&g_t[eb + j0], *(unsigned*)&ha, *(unsigned*)&hb);
            st8_cs(&g_t[eb + j1], *(unsigned*)&hc, *(unsigned*)&hd);
            #pragma unroll
            for (int i = 0; i < 8; i++) {
                ssum[i] += tv[i];
                sssq[i] = fmaf(tv[i], tv[i], sssq[i]);
            }
            // sigmoid gate from fp16 w0
            float2 wa01 = __half22float2(*(const __half2*)&w0h[row * PITCH16 + j0]);
            float2 wa23 = __half22float2(*(const __half2*)&w0h[row * PITCH16 + j0 + 2]);
            float2 wb01 = __half22float2(*(const __half2*)&w0h[row * PITCH16 + j1]);
            float2 wb23 = __half22float2(*(const __half2*)&w0h[row * PITCH16 + j1 + 2]);
            float* sp = g_sums + (size_t)s_use * 64;
            red4(sp + j0, sigmoidf(wa01.x) * x2a.x, sigmoidf(wa01.y) * x2a.y,
                          sigmoidf(wa23.x) * x2a.z, sigmoidf(wa23.y) * x2a.w);
            red4(sp + j1, sigmoidf(wb01.x) * x2b.x, sigmoidf(wb01.y) * x2b.y,
                          sigmoidf(wb23.x) * x2b.z, sigmoidf(wb23.y) * x2b.w);
            if (c8 == 0) atomicAdd(&g_cnt[s_use], 1.0f);
        }
        buf ^= 1;
    }

    // ---- flush BN stats: warp shfl -> smem block reduction -> 128 atomics/block ----
    #pragma unroll
    for (int i = 0; i < 8; i++) {
        ssum[i] += __shfl_xor_sync(0xffffffffu, ssum[i], 8);
        ssum[i] += __shfl_xor_sync(0xffffffffu, ssum[i], 16);
        sssq[i] += __shfl_xor_sync(0xffffffffu, sssq[i], 8);
        sssq[i] += __shfl_xor_sync(0xffffffffu, sssq[i], 16);
    }
    __syncthreads();
    float* redb = sm;              // reuse w1s region: [8 warps][128 stats]
    if ((lane & 24) == 0) {
        #pragma unroll
        for (int i = 0; i < 8; i++) {
            int col = (i < 4) ? (j0 + i) : (j1 + i - 4);
            redb[warp * 128 + col] = ssum[i];
            redb[warp * 128 + 64 + col] = sssq[i];
        }
    }
    __syncthreads();
    if (tid < 128) {
        float v = 0.0f;
        #pragma unroll
        for (int w = 0; w < 8; w++) v += redb[w * 128 + tid];
        atomicAdd(&g_estat[tid], v);
    }
}

// ------------------- kernel 4: node pre-BN + stats (smem-reduced atomics) -------------------
#define NS_BLOCKS 512
__global__ void node_stats() {
    __shared__ float redb[8 * 128];
    int tid = threadIdx.x;
    int t = blockIdx.x * 256 + tid;
    int c = (tid & 15) * 4;
    int stride = (NS_BLOCKS * 256) >> 4;
    float s0 = 0, s1 = 0, s2 = 0, s3 = 0, q0 = 0, q1 = 0, q2 = 0, q3 = 0;
    for (int n = t >> 4; n < N_NODES; n += stride) {
        size_t off = (size_t)n * 64 + c;
        float4 a = *(const float4*)&g_x1[off];
        float4 g = *(const float4*)&g_sums[off];
        float inv = 1.0f / fmaxf(g_cnt[n], 1.0f);
        float4 y;
        y.x = fmaf(g.x, inv, a.x);
        y.y = fmaf(g.y, inv, a.y);
        y.z = fmaf(g.z, inv, a.z);
        y.w = fmaf(g.w, inv, a.w);
        *(float4*)&g_y[off] = y;
        s0 += y.x; q0 = fmaf(y.x, y.x, q0);
        s1 += y.y; q1 = fmaf(y.y, y.y, q1);
        s2 += y.z; q2 = fmaf(y.z, y.z, q2);
        s3 += y.w; q3 = fmaf(y.w, y.w, q3);
    }
    s0 += __shfl_xor_sync(0xffffffffu, s0, 16);
    s1 += __shfl_xor_sync(0xffffffffu, s1, 16);
    s2 += __shfl_xor_sync(0xffffffffu, s2, 16);
    s3 += __shfl_xor_sync(0xffffffffu, s3, 16);
    q0 += __shfl_xor_sync(0xffffffffu, q0, 16);
    q1 += __shfl_xor_sync(0xffffffffu, q1, 16);
    q2 += __shfl_xor_sync(0xffffffffu, q2, 16);
    q3 += __shfl_xor_sync(0xffffffffu, q3, 16);
    int warp = tid >> 5, lane = tid & 31;
    if (lane < 16) {
        redb[warp * 128 + c + 0] = s0;
        redb[warp * 128 + c + 1] = s1;
        redb[warp * 128 + c + 2] = s2;
        redb[warp * 128 + c + 3] = s3;
        redb[warp * 128 + 64 + c + 0] = q0;
        redb[warp * 128 + 64 + c + 1] = q1;
        redb[warp * 128 + 64 + c + 2] = q2;
        redb[warp * 128 + 64 + c + 3] = q3;
    }
    __syncthreads();
    if (tid < 128) {
        float v = 0.0f;
        #pragma unroll
        for (int w = 0; w < 8; w++) v += redb[w * 128 + tid];
        atomicAdd(&g_nstat[tid], v);
    }
}

// ------------------- kernel 5: fused BN + SiLU + residual -------------------
#define APPLY_NODE_BLOCKS 512
#define APPLY_EDGE_BLOCKS 4096
__global__ void apply_fused(const float* __restrict__ x, const float* __restrict__ ea,
                            const float* __restrict__ vg, const float* __restrict__ vb,
                            const float* __restrict__ eg, const float* __restrict__ eb,
                            float* __restrict__ out) {
    bool isEdge = blockIdx.x >= APPLY_NODE_BLOCKS;
    int bid     = isEdge ? (blockIdx.x - APPLY_NODE_BLOCKS) : blockIdx.x;
    const float* stat  = isEdge ? g_estat : g_nstat;
    float invRows = isEdge ? (1.0f / (float)N_EDGES) : (1.0f / (float)N_NODES);
    const float* gamma = isEdge ? eg : vg;
    const float* beta  = isEdge ? eb : vb;

    int t = bid * blockDim.x + threadIdx.x;
    int c = (t & 15) * 4;
    float A[4], B[4];
    #pragma unroll
    for (int i = 0; i < 4; i++) {
        float m = stat[c + i] * invRows;
        float var = stat[64 + c + i] * invRows - m * m;
        float rs = rsqrtf(var + 1e-5f);
        float gs = gamma[c + i] * rs;
        A[i] = gs;
        B[i] = fmaf(-m, gs, beta[c + i]);
    }
    if (!isEdge) {
        int stride = (APPLY_NODE_BLOCKS * 256) >> 4;
        for (int r = t >> 4; r < N_NODES; r += stride) {
            size_t off = (size_t)r * 64 + c;
            float4 y = __ldcs((const float4*)(g_y + off));
            float4 xv = __ldcs((const float4*)(x + off));
            float z0 = fmaf(y.x, A[0], B[0]);
            float z1 = fmaf(y.y, A[1], B[1]);
            float z2 = fmaf(y.z, A[2], B[2]);
            float z3 = fmaf(y.w, A[3], B[3]);
            float4 o;
            o.x = xv.x + z0 * sigmoidf(z0);
            o.y = xv.y + z1 * sigmoidf(z1);
            o.z = xv.z + z2 * sigmoidf(z2);
            o.w = xv.w + z3 * sigmoidf(z3);
            __stcs((float4*)(out + off), o);
        }
    } else {
        float* ob = out + (size_t)N_NODES * DD;
        int stride = (APPLY_EDGE_BLOCKS * 256) >> 4;
        for (int r = t >> 4; r < N_EDGES; r += stride) {
            size_t off = (size_t)r * 64 + c;
            uint2 u = __ldcs((const uint2*)(g_t + off));
            __half2 h0 = *(__half2*)&u.x;
            __half2 h1 = *(__half2*)&u.y;
            float2 y01 = __half22float2(h0);
            float2 y23 = __half22float2(h1);
            float4 xv = __ldcs((const float4*)(ea + off));
            float z0 = fmaf(y01.x, A[0], B[0]);
            float z1 = fmaf(y01.y, A[1], B[1]);
            float z2 = fmaf(y23.x, A[2], B[2]);
            float z3 = fmaf(y23.y, A[3], B[3]);
            float4 o;
            o.x = xv.x + z0 * sigmoidf(z0);
            o.y = xv.y + z1 * sigmoidf(z1);
            o.z = xv.z + z2 * sigmoidf(z2);
            o.w = xv.w + z3 * sigmoidf(z3);
            __stcs((float4*)(ob + off), o);
        }
    }
}

// ------------------- launch -------------------
extern "C" void kernel_launch(void* const* d_in, const int* in_sizes, int n_in,
                              void* d_out, int out_size) {
    const float* x   = (const float*)d_in[0];
    const float* ea  = (const float*)d_in[1];
    const float* W1  = (const float*)d_in[2];
    const float* b1  = (const float*)d_in[3];
    const float* W2  = (const float*)d_in[4];
    const float* b2  = (const float*)d_in[5];
    const float* W3  = (const float*)d_in[6];
    const float* b3  = (const float*)d_in[7];
    const float* W4  = (const float*)d_in[8];
    const float* b4  = (const float*)d_in[9];
    const float* We  = (const float*)d_in[10];
    const float* be  = (const float*)d_in[11];
    const float* vg  = (const float*)d_in[12];
    const float* vb  = (const float*)d_in[13];
    const float* eg  = (const float*)d_in[14];
    const float* ebt = (const float*)d_in[15];
    const int*   ei  = (const int*)d_in[16];
    const int* srcp = ei;
    const int* dstp = ei + N_EDGES;
    float* out = (float*)d_out;

    cudaFuncSetAttribute(edge_pass1, cudaFuncAttributeMaxDynamicSharedMemorySize, EDGE_SMEM);

    prepack<<<16, 256>>>(W1, W2, W3, W4, We, b1, b2, b3, b4);
    node_gemm<<<296, 256>>>(x);
    edge_pass1<<<296, 256, EDGE_SMEM>>>(ea, srcp, dstp, be);
    node_stats<<<NS_BLOCKS, 256>>>();
    apply_fused<<<APPLY_NODE_BLOCKS + APPLY_EDGE_BLOCKS, 256>>>(x, ea, vg, vb, eg, ebt, out);
}

// round 12
// speedup vs baseline: 1.7850x; 1.1368x over previous
#include <cuda_runtime.h>
#include <cuda_fp16.h>
#include <cstdint>

#define N_NODES 100000
#define N_EDGES 1600000
#define DD 64

typedef unsigned long long u64;

// ------------------- scratch (static device globals; no allocation) -------------------
__device__ float g_x1[(size_t)N_NODES * DD];        // x@W1^T+b1 (fp32: feeds node_stats)
__device__ __half g_x3h[(size_t)N_NODES * DD];      // x@W3^T+b3 (fp16 gather table)
__device__ __half g_x24h[(size_t)N_NODES * 2 * DD]; // per node: [x2 | x4] fp16 gather table
__device__ float g_y[(size_t)N_NODES * DD];         // x1 + aggregated (pre-BN node)
__device__ float g_sums[(size_t)N_NODES * DD];      // scatter-add accumulator
__device__ float g_cnt[N_NODES];                    // per-src edge counts
__device__ __half g_t[(size_t)N_EDGES * DD];        // pre-BN edge tensor (fp16, 204.8 MB)
__device__ float g_bN[256];
__device__ __half g_WNH[256 * 64];                  // stacked [W1;W2;W3;W4] row-major fp16
__device__ __half g_WeH[64 * 64];                   // We row-major (j*64+k) in fp16
__device__ float g_nstat[128];                      // node: sum[64], ssq[64]
__device__ float g_estat[128];                      // edge: sum[64], ssq[64]

// ------------------- helpers -------------------
__device__ __forceinline__ float sigmoidf(float x) { return 1.0f / (1.0f + __expf(-x)); }

__device__ __forceinline__ unsigned sm2u(const void* p) {
    return (unsigned)__cvta_generic_to_shared(p);
}
__device__ __forceinline__ u64 mkpolicy_evict_first() {
    u64 p;
    asm("createpolicy.fractional.L2::evict_first.b64 %0, 1.0;" : "=l"(p));
    return p;
}
__device__ __forceinline__ void cpa16(unsigned s, const void* g) {
    asm volatile("cp.async.cg.shared.global [%0], [%1], 16;" :: "r"(s), "l"(g));
}
__device__ __forceinline__ void cpa16_pol(unsigned s, const void* g, u64 pol) {
    asm volatile("cp.async.cg.shared.global.L2::cache_hint [%0], [%1], 16, %2;"
                 :: "r"(s), "l"(g), "l"(pol));
}
__device__ __forceinline__ void cpa_commit() {
    asm volatile("cp.async.commit_group;");
}
__device__ __forceinline__ void cpa_wait0() {
    asm volatile("cp.async.wait_group 0;");
}
__device__ __forceinline__ void red4(float* p, float a, float b, float c, float d) {
    asm volatile("red.global.add.v4.f32 [%0], {%1,%2,%3,%4};"
                 :: "l"(p), "f"(a), "f"(b), "f"(c), "f"(d) : "memory");
}
__device__ __forceinline__ void st8_cs(__half* p, unsigned a, unsigned b) {
    asm volatile("st.global.cs.v2.b32 [%0], {%1,%2};" :: "l"(p), "r"(a), "r"(b) : "memory");
}
__device__ __forceinline__ void ldmat4(unsigned& r0, unsigned& r1, unsigned& r2, unsigned& r3,
                                       unsigned addr) {
    asm volatile("ldmatrix.sync.aligned.m8n8.x4.shared.b16 {%0,%1,%2,%3}, [%4];"
                 : "=r"(r0), "=r"(r1), "=r"(r2), "=r"(r3) : "r"(addr));
}
__device__ __forceinline__ void mma16816(float& d0, float& d1, float& d2, float& d3,
                                         unsigned a0, unsigned a1, unsigned a2, unsigned a3,
                                         unsigned b0, unsigned b1) {
    asm volatile("mma.sync.aligned.m16n8k16.row.col.f32.f16.f16.f32 "
                 "{%0,%1,%2,%3},{%4,%5,%6,%7},{%8,%9},{%0,%1,%2,%3};"
                 : "+f"(d0), "+f"(d1), "+f"(d2), "+f"(d3)
                 : "r"(a0), "r"(a1), "r"(a2), "r"(a3), "r"(b0), "r"(b1));
}
__device__ __forceinline__ float2 h2f(unsigned u) {
    return __half22float2(*(__half2*)&u);
}

// ------------------- kernel 1: prepack weights (+ zero stats) -------------------
__global__ void prepack(const float* __restrict__ W1, const float* __restrict__ W2,
                        const float* __restrict__ W3, const float* __restrict__ W4,
                        const float* __restrict__ We, const float* __restrict__ b1,
                        const float* __restrict__ b2, const float* __restrict__ b3,
                        const float* __restrict__ b4) {
    int t = blockIdx.x * blockDim.x + threadIdx.x;
    if (t < 4096) {
        g_WNH[t]         = __float2half(W1[t]);   // rows 0..63
        g_WNH[4096 + t]  = __float2half(W2[t]);   // rows 64..127
        g_WNH[8192 + t]  = __float2half(W3[t]);   // rows 128..191
        g_WNH[12288 + t] = __float2half(W4[t]);   // rows 192..255
        g_WeH[t] = __float2half(We[t]);           // row-major [j][k]
    }
    if (t < 64) {
        g_bN[t] = b1[t]; g_bN[64 + t] = b2[t]; g_bN[128 + t] = b3[t]; g_bN[192 + t] = b4[t];
    }
    if (t < 128) { g_nstat[t] = 0.0f; g_estat[t] = 0.0f; }
}

// ------------------- kernel 2: node GEMMs on tensor pipe (x1 fp32; x2,x3,x4 fp16) -------------------
#define NPITCH16 72
#define NODE_TILES ((N_NODES + 127) / 128)
__global__ __launch_bounds__(256, 2) void node_gemm(const float* __restrict__ x) {
    __shared__ __align__(16) __half xh[128 * NPITCH16];
    int tid = threadIdx.x, warp = tid >> 5, lane = tid & 31;
    int t4 = lane & 3;

    // ---- loop-invariant B fragments: 4 n8 groups of this warp's 32-col strip ----
    unsigned BF[32];
    float bb0[4], bb1[4];
    float* f32b[4];
    __half* f16b[4];
    int strd[4];
    bool is32[4];
    #pragma unroll
    for (int g = 0; g < 4; g++) {
        int j = warp * 32 + g * 8 + (lane >> 2);
        #pragma unroll
        for (int kt = 0; kt < 4; kt++) {
            BF[g * 8 + kt * 2]     = *(const unsigned*)&g_WNH[j * 64 + kt * 16 + 2 * t4];
            BF[g * 8 + kt * 2 + 1] = *(const unsigned*)&g_WNH[j * 64 + kt * 16 + 8 + 2 * t4];
        }
        int jc = warp * 32 + g * 8 + 2 * t4;         // this thread's output column pair
        bb0[g] = g_bN[jc]; bb1[g] = g_bN[jc + 1];
        f32b[g] = nullptr; f16b[g] = nullptr;
        if (jc < 64)       { is32[g] = true;  f32b[g] = g_x1 + jc;               strd[g] = 64;  }
        else if (jc < 128) { is32[g] = false; f16b[g] = g_x24h + (jc - 64);       strd[g] = 128; }
        else if (jc < 192) { is32[g] = false; f16b[g] = g_x3h + (jc - 128);       strd[g] = 64;  }
        else               { is32[g] = false; f16b[g] = g_x24h + 64 + (jc - 192); strd[g] = 128; }
    }

    unsigned ldbase = sm2u(xh) + (unsigned)(((lane & 15) * NPITCH16 + (lane >> 4) * 8) * 2);
    const float4 z4 = make_float4(0.f, 0.f, 0.f, 0.f);

    for (int tile = blockIdx.x; tile < NODE_TILES; tile += gridDim.x) {
        int base = tile * 128;
        for (int f = tid; f < 2048; f += 256) {
            int row = f >> 4, c4 = f & 15;
            int n = base + row;
            float4 v = z4;
            if (n < N_NODES) {
                v = ((const float4*)(x + (size_t)n * 64))[c4];
                ((float4*)(g_sums + (size_t)n * 64))[c4] = z4;
            }
            __half2 h0 = __floats2half2_rn(v.x, v.y);
            __half2 h1 = __floats2half2_rn(v.z, v.w);
            uint2 pk;
            pk.x = *(unsigned*)&h0;
            pk.y = *(unsigned*)&h1;
            *(uint2*)&xh[row * NPITCH16 + c4 * 4] = pk;
        }
        if (tid < 128 && base + tid < N_NODES) g_cnt[base + tid] = 0.0f;
        __syncthreads();

        #pragma unroll
        for (int mt = 0; mt < 8; mt++) {
            unsigned A[16];
            #pragma unroll
            for (int kt = 0; kt < 4; kt++)
                ldmat4(A[kt * 4], A[kt * 4 + 1], A[kt * 4 + 2], A[kt * 4 + 3],
                       ldbase + (unsigned)(mt * 16 * NPITCH16 * 2 + kt * 32));
            int r0 = mt * 16 + (lane >> 2);
            int n0 = base + r0, n1 = n0 + 8;
            #pragma unroll
            for (int g = 0; g < 4; g++) {
                float d0 = 0.f, d1 = 0.f, d2 = 0.f, d3 = 0.f;
                #pragma unroll
                for (int kt = 0; kt < 4; kt++)
                    mma16816(d0, d1, d2, d3, A[kt * 4], A[kt * 4 + 1], A[kt * 4 + 2], A[kt * 4 + 3],
                             BF[g * 8 + kt * 2], BF[g * 8 + kt * 2 + 1]);
                if (is32[g]) {
                    if (n0 < N_NODES)
                        *(float2*)(f32b[g] + (size_t)n0 * strd[g]) = make_float2(d0 + bb0[g], d1 + bb1[g]);
                    if (n1 < N_NODES)
                        *(float2*)(f32b[g] + (size_t)n1 * strd[g]) = make_float2(d2 + bb0[g], d3 + bb1[g]);
                } else {
                    if (n0 < N_NODES)
                        *(__half2*)(f16b[g] + (size_t)n0 * strd[g]) = __floats2half2_rn(d0 + bb0[g], d1 + bb1[g]);
                    if (n1 < N_NODES)
                        *(__half2*)(f16b[g] + (size_t)n1 * strd[g]) = __floats2half2_rn(d2 + bb0[g], d3 + bb1[g]);
                }
            }
        }
        __syncthreads();
    }
}

// ------------------- kernel 3: edge pass 1 (tensor-core GEMV, fp16 gathers) -------------------
#define W1S_OFF 0
#define W0C_OFF 8704
#define W0H_OFF 17408
#define BES_OFF 22016
#define IDX_OFF 22080
#define EDGE_SMEM ((IDX_OFF + 512) * 4)     // 90368 B
#define ETILES (N_EDGES / 128)
#define PITCH32 68
#define PITCH16 72

__device__ __forceinline__ void prefetch_tile(float* w0buf, int* sbuf, int* dbuf,
                                              const float* __restrict__ ea,
                                              const int* __restrict__ srcp,
                                              const int* __restrict__ dstp,
                                              int base, int tid, u64 pol) {
    if (tid < 32) {
        cpa16(sm2u(sbuf + tid * 4), srcp + base + tid * 4);
    } else if (tid < 64) {
        int i = tid - 32;
        cpa16(sm2u(dbuf + i * 4), dstp + base + i * 4);
    }
    const float4* gp = (const float4*)(ea + (size_t)base * DD);
    #pragma unroll
    for (int u = 0; u < 8; u++) {
        int f = tid + u * 256;                 // 2048 float4s = full 128x64 tile
        int row = f >> 4, c4 = f & 15;
        cpa16_pol(sm2u(w0buf + row * PITCH32 + c4 * 4), gp + f, pol);
    }
}

__global__ __launch_bounds__(256, 2)
void edge_pass1(const float* __restrict__ ea, const int* __restrict__ srcp,
                const int* __restrict__ dstp, const float* __restrict__ be) {
    extern __shared__ float sm[];
    float* w1s = sm + W1S_OFF;
    float* w0c = sm + W0C_OFF;
    __half* w0h = (__half*)(sm + W0H_OFF);
    float* beS = sm + BES_OFF;
    int* sS = (int*)(sm + IDX_OFF);        // 2 x 128
    int* dS = sS + 256;                    // 2 x 128

    int tid = threadIdx.x, warp = tid >> 5, lane = tid & 31;
    u64 pol = mkpolicy_evict_first();
    if (tid < 64) beS[tid] = be[tid];

    // ---- per-warp B fragments (n-strip = cols 8*warp..8*warp+7), loop-invariant ----
    unsigned BF[8];
    {
        int g = lane >> 2, t4 = lane & 3;
        int j = warp * 8 + g;
        #pragma unroll
        for (int kt = 0; kt < 4; kt++) {
            BF[kt * 2]     = *(const unsigned*)&g_WeH[j * 64 + kt * 16 + 2 * t4];
            BF[kt * 2 + 1] = *(const unsigned*)&g_WeH[j * 64 + kt * 16 + 8 + 2 * t4];
        }
    }

    prefetch_tile(w0c, sS, dS, ea, srcp, dstp, blockIdx.x * 128, tid, pol);
    cpa_commit();
    __syncthreads();

    float be0, be1;
    { int t4 = lane & 3; be0 = beS[warp * 8 + 2 * t4]; be1 = beS[warp * 8 + 2 * t4 + 1]; }

    int c8 = tid & 7, rq = tid >> 3;
    int j0 = c8 * 4, j1 = 32 + c8 * 4;

    float ssum[8], sssq[8];
    #pragma unroll
    for (int i = 0; i < 8; i++) { ssum[i] = 0.0f; sssq[i] = 0.0f; }

    unsigned ldbase = sm2u(w0h) + (unsigned)(((lane & 15) * PITCH16 + (lane >> 4) * 8) * 2);

    int buf = 0;
    for (int tile = blockIdx.x; tile < ETILES; tile += gridDim.x) {
        cpa_wait0();
        __syncthreads();
        int* sC = sS + buf * 128;
        int* dC = dS + buf * 128;
        int base = tile * 128;

        // ---- hoist indices + issue row-0 gathers (fp16 tables, 8B loads) ----
        int sidx[4], didx[4];
        #pragma unroll
        for (int rr = 0; rr < 4; rr++) {
            sidx[rr] = sC[rq + 32 * rr];
            didx[rr] = dC[rq + 32 * rr];
        }
        const __half* x3p = g_x3h + (size_t)sidx[0] * 64;
        const __half* x24p = g_x24h + (size_t)didx[0] * 128;
        uint2 p0 = *(const uint2*)(x3p + j0);
        uint2 p1 = *(const uint2*)(x3p + j1);
        uint2 p2 = *(const uint2*)(x24p + j0);
        uint2 p3 = *(const uint2*)(x24p + j1);
        uint2 p4 = *(const uint2*)(x24p + 64 + j0);
        uint2 p5 = *(const uint2*)(x24p + 64 + j1);

        // ---- convert fp32 tile -> fp16 tile ----
        #pragma unroll
        for (int u = 0; u < 8; u++) {
            int f = tid + u * 256;
            int row = f >> 4, c4 = f & 15;
            float4 v = *(const float4*)&w0c[row * PITCH32 + c4 * 4];
            __half2 h0 = __floats2half2_rn(v.x, v.y);
            __half2 h1 = __floats2half2_rn(v.z, v.w);
            uint2 pk;
            pk.x = *(unsigned*)&h0;
            pk.y = *(unsigned*)&h1;
            *(uint2*)&w0h[row * PITCH16 + c4 * 4] = pk;
        }
        __syncthreads();   // w0h ready; w0c free for next prefetch

        // ---- issue next tile's prefetch ----
        int ntile = tile + gridDim.x;
        if (ntile < ETILES)
            prefetch_tile(w0c, sS + (buf ^ 1) * 128, dS + (buf ^ 1) * 128,
                          ea, srcp, dstp, ntile * 128, tid, pol);
        cpa_commit();

        // ---- GEMV on tensor pipe ----
        #pragma unroll
        for (int mt = 0; mt < 8; mt++) {
            float d0 = 0.f, d1 = 0.f, d2 = 0.f, d3 = 0.f;
            #pragma unroll
            for (int kt = 0; kt < 4; kt++) {
                unsigned a0, a1, a2, a3;
                ldmat4(a0, a1, a2, a3, ldbase + (unsigned)(mt * 16 * PITCH16 * 2 + kt * 32));
                mma16816(d0, d1, d2, d3, a0, a1, a2, a3, BF[kt * 2], BF[kt * 2 + 1]);
            }
            int r0 = mt * 16 + (lane >> 2);
            int cc = warp * 8 + 2 * (lane & 3);
            *(float2*)&w1s[r0 * PITCH32 + cc] = make_float2(d0 + be0, d1 + be1);
            *(float2*)&w1s[(r0 + 8) * PITCH32 + cc] = make_float2(d2 + be0, d3 + be1);
        }
        __syncthreads();   // w1s visible to all

        // ---- combine: 4 rows, 1-deep pipelined fp16 gathers ----
        #pragma unroll
        for (int rr = 0; rr < 4; rr++) {
            int row = rq + 32 * rr;
            uint2 q0 = p0, q1 = p1, q2 = p2, q3 = p3, q4 = p4, q5 = p5;
            int s_use = sidx[rr];
            if (rr < 3) {
                const __half* nx3 = g_x3h + (size_t)sidx[rr + 1] * 64;
                const __half* nx24 = g_x24h + (size_t)didx[rr + 1] * 128;
                p0 = *(const uint2*)(nx3 + j0);
                p1 = *(const uint2*)(nx3 + j1);
                p2 = *(const uint2*)(nx24 + j0);
                p3 = *(const uint2*)(nx24 + j1);
                p4 = *(const uint2*)(nx24 + 64 + j0);
                p5 = *(const uint2*)(nx24 + 64 + j1);
            }

            float2 x3_01 = h2f(q0.x), x3_23 = h2f(q0.y);
            float2 x3_45 = h2f(q1.x), x3_67 = h2f(q1.y);
            float2 x4_01 = h2f(q4.x), x4_23 = h2f(q4.y);
            float2 x4_45 = h2f(q5.x), x4_67 = h2f(q5.y);

            float2 w1_0 = *(const float2*)&w1s[row * PITCH32 + j0];
            float2 w1_1 = *(const float2*)&w1s[row * PITCH32 + j0 + 2];
            float2 w1_2 = *(const float2*)&w1s[row * PITCH32 + j1];
            float2 w1_3 = *(const float2*)&w1s[row * PITCH32 + j1 + 2];
            float tv[8];
            tv[0] = w1_0.x + x3_01.x + x4_01.x;
            tv[1] = w1_0.y + x3_01.y + x4_01.y;
            tv[2] = w1_1.x + x3_23.x + x4_23.x;
            tv[3] = w1_1.y + x3_23.y + x4_23.y;
            tv[4] = w1_2.x + x3_45.x + x4_45.x;
            tv[5] = w1_2.y + x3_45.y + x4_45.y;
            tv[6] = w1_3.x + x3_67.x + x4_67.x;
            tv[7] = w1_3.y + x3_67.y + x4_67.y;
            size_t eb = (size_t)(base + row) * 64;
            __half2 ha = __floats2half2_rn(tv[0], tv[1]);
            __half2 hb = __floats2half2_rn(tv[2], tv[3]);
            __half2 hc = __floats2half2_rn(tv[4], tv[5]);
            __half2 hd = __floats2half2_rn(tv[6], tv[7]);
            st8_cs(&g_t[eb + j0], *(unsigned*)&ha, *(unsigned*)&hb);
            st8_cs(&g_t[eb + j1], *(unsigned*)&hc, *(unsigned*)&hd);
            #pragma unroll
            for (int i = 0; i < 8; i++) {
                ssum[i] += tv[i];
                sssq[i] = fmaf(tv[i], tv[i], sssq[i]);
            }
            // sigmoid gate from fp16 w0, x2 from fp16 gather
            float2 wa01 = __half22float2(*(const __half2*)&w0h[row * PITCH16 + j0]);
            float2 wa23 = __half22float2(*(const __half2*)&w0h[row * PITCH16 + j0 + 2]);
            float2 wb01 = __half22float2(*(const __half2*)&w0h[row * PITCH16 + j1]);
            float2 wb23 = __half22float2(*(const __half2*)&w0h[row * PITCH16 + j1 + 2]);
            float2 x2_01 = h2f(q2.x), x2_23 = h2f(q2.y);
            float2 x2_45 = h2f(q3.x), x2_67 = h2f(q3.y);
            float* sp = g_sums + (size_t)s_use * 64;
            red4(sp + j0, sigmoidf(wa01.x) * x2_01.x, sigmoidf(wa01.y) * x2_01.y,
                          sigmoidf(wa23.x) * x2_23.x, sigmoidf(wa23.y) * x2_23.y);
            red4(sp + j1, sigmoidf(wb01.x) * x2_45.x, sigmoidf(wb01.y) * x2_45.y,
                          sigmoidf(wb23.x) * x2_67.x, sigmoidf(wb23.y) * x2_67.y);
            if (c8 == 0) atomicAdd(&g_cnt[s_use], 1.0f);
        }
        buf ^= 1;
    }

    // ---- flush BN stats ----
    #pragma unroll
    for (int i = 0; i < 8; i++) {
        ssum[i] += __shfl_xor_sync(0xffffffffu, ssum[i], 8);
        ssum[i] += __shfl_xor_sync(0xffffffffu, ssum[i], 16);
        sssq[i] += __shfl_xor_sync(0xffffffffu, sssq[i], 8);
        sssq[i] += __shfl_xor_sync(0xffffffffu, sssq[i], 16);
    }
    __syncthreads();
    float* redb = sm;
    if ((lane & 24) == 0) {
        #pragma unroll
        for (int i = 0; i < 8; i++) {
            int col = (i < 4) ? (j0 + i) : (j1 + i - 4);
            redb[warp * 128 + col] = ssum[i];
            redb[warp * 128 + 64 + col] = sssq[i];
        }
    }
    __syncthreads();
    if (tid < 128) {
        float v = 0.0f;
        #pragma unroll
        for (int w = 0; w < 8; w++) v += redb[w * 128 + tid];
        atomicAdd(&g_estat[tid], v);
    }
}

// ------------------- kernel 4: node pre-BN + stats (smem-reduced atomics) -------------------
#define NS_BLOCKS 512
__global__ void node_stats() {
    __shared__ float redb[8 * 128];
    int tid = threadIdx.x;
    int t = blockIdx.x * 256 + tid;
    int c = (tid & 15) * 4;
    int stride = (NS_BLOCKS * 256) >> 4;
    float s0 = 0, s1 = 0, s2 = 0, s3 = 0, q0 = 0, q1 = 0, q2 = 0, q3 = 0;
    for (int n = t >> 4; n < N_NODES; n += stride) {
        size_t off = (size_t)n * 64 + c;
        float4 a = *(const float4*)&g_x1[off];
        float4 g = *(const float4*)&g_sums[off];
        float inv = 1.0f / fmaxf(g_cnt[n], 1.0f);
        float4 y;
        y.x = fmaf(g.x, inv, a.x);
        y.y = fmaf(g.y, inv, a.y);
        y.z = fmaf(g.z, inv, a.z);
        y.w = fmaf(g.w, inv, a.w);
        *(float4*)&g_y[off] = y;
        s0 += y.x; q0 = fmaf(y.x, y.x, q0);
        s1 += y.y; q1 = fmaf(y.y, y.y, q1);
        s2 += y.z; q2 = fmaf(y.z, y.z, q2);
        s3 += y.w; q3 = fmaf(y.w, y.w, q3);
    }
    s0 += __shfl_xor_sync(0xffffffffu, s0, 16);
    s1 += __shfl_xor_sync(0xffffffffu, s1, 16);
    s2 += __shfl_xor_sync(0xffffffffu, s2, 16);
    s3 += __shfl_xor_sync(0xffffffffu, s3, 16);
    q0 += __shfl_xor_sync(0xffffffffu, q0, 16);
    q1 += __shfl_xor_sync(0xffffffffu, q1, 16);
    q2 += __shfl_xor_sync(0xffffffffu, q2, 16);
    q3 += __shfl_xor_sync(0xffffffffu, q3, 16);
    int warp = tid >> 5, lane = tid & 31;
    if (lane < 16) {
        redb[warp * 128 + c + 0] = s0;
        redb[warp * 128 + c + 1] = s1;
        redb[warp * 128 + c + 2] = s2;
        redb[warp * 128 + c + 3] = s3;
        redb[warp * 128 + 64 + c + 0] = q0;
        redb[warp * 128 + 64 + c + 1] = q1;
        redb[warp * 128 + 64 + c + 2] = q2;
        redb[warp * 128 + 64 + c + 3] = q3;
    }
    __syncthreads();
    if (tid < 128) {
        float v = 0.0f;
        #pragma unroll
        for (int w = 0; w < 8; w++) v += redb[w * 128 + tid];
        atomicAdd(&g_nstat[tid], v);
    }
}

// ------------------- kernel 5: fused BN + SiLU + residual (8 cols/thread) -------------------
#define APPLY_NODE_BLOCKS 512
#define APPLY_EDGE_BLOCKS 4096
__global__ void apply_fused(const float* __restrict__ x, const float* __restrict__ ea,
                            const float* __restrict__ vg, const float* __restrict__ vb,
                            const float* __restrict__ eg, const float* __restrict__ eb,
                            float* __restrict__ out) {
    bool isEdge = blockIdx.x >= APPLY_NODE_BLOCKS;
    int bid     = isEdge ? (blockIdx.x - APPLY_NODE_BLOCKS) : blockIdx.x;
    const float* stat  = isEdge ? g_estat : g_nstat;
    float invRows = isEdge ? (1.0f / (float)N_EDGES) : (1.0f / (float)N_NODES);
    const float* gamma = isEdge ? eg : vg;
    const float* beta  = isEdge ? eb : vb;

    int t = bid * blockDim.x + threadIdx.x;
    int c = (t & 7) * 8;
    float A[8], B[8];
    #pragma unroll
    for (int i = 0; i < 8; i++) {
        float m = stat[c + i] * invRows;
        float var = stat[64 + c + i] * invRows - m * m;
        float rs = rsqrtf(var + 1e-5f);
        float gs = gamma[c + i] * rs;
        A[i] = gs;
        B[i] = fmaf(-m, gs, beta[c + i]);
    }
    if (!isEdge) {
        int stride = (APPLY_NODE_BLOCKS * 256) >> 3;
        for (int r = t >> 3; r < N_NODES; r += stride) {
            size_t off = (size_t)r * 64 + c;
            float4 y0 = __ldcs((const float4*)(g_y + off));
            float4 y1 = __ldcs((const float4*)(g_y + off + 4));
            float4 x0 = __ldcs((const float4*)(x + off));
            float4 x1 = __ldcs((const float4*)(x + off + 4));
            float yv[8] = { y0.x, y0.y, y0.z, y0.w, y1.x, y1.y, y1.z, y1.w };
            float xv[8] = { x0.x, x0.y, x0.z, x0.w, x1.x, x1.y, x1.z, x1.w };
            float ov[8];
            #pragma unroll
            for (int i = 0; i < 8; i++) {
                float z = fmaf(yv[i], A[i], B[i]);
                ov[i] = xv[i] + z * sigmoidf(z);
            }
            __stcs((float4*)(out + off), make_float4(ov[0], ov[1], ov[2], ov[3]));
            __stcs((float4*)(out + off + 4), make_float4(ov[4], ov[5], ov[6], ov[7]));
        }
    } else {
        float* ob = out + (size_t)N_NODES * DD;
        int stride = (APPLY_EDGE_BLOCKS * 256) >> 3;
        for (int r = t >> 3; r < N_EDGES; r += stride) {
            size_t off = (size_t)r * 64 + c;
            uint4 u = __ldcs((const uint4*)(g_t + off));
            float2 y01 = h2f(u.x), y23 = h2f(u.y), y45 = h2f(u.z), y67 = h2f(u.w);
            float4 x0 = __ldcs((const float4*)(ea + off));
            float4 x1 = __ldcs((const float4*)(ea + off + 4));
            float yv[8] = { y01.x, y01.y, y23.x, y23.y, y45.x, y45.y, y67.x, y67.y };
            float xv[8] = { x0.x, x0.y, x0.z, x0.w, x1.x, x1.y, x1.z, x1.w };
            float ov[8];
            #pragma unroll
            for (int i = 0; i < 8; i++) {
                float z = fmaf(yv[i], A[i], B[i]);
                ov[i] = xv[i] + z * sigmoidf(z);
            }
            __stcs((float4*)(ob + off), make_float4(ov[0], ov[1], ov[2], ov[3]));
            __stcs((float4*)(ob + off + 4), make_float4(ov[4], ov[5], ov[6], ov[7]));
        }
    }
}

// ------------------- launch -------------------
extern "C" void kernel_launch(void* const* d_in, const int* in_sizes, int n_in,
                              void* d_out, int out_size) {
    const float* x   = (const float*)d_in[0];
    const float* ea  = (const float*)d_in[1];
    const float* W1  = (const float*)d_in[2];
    const float* b1  = (const float*)d_in[3];
    const float* W2  = (const float*)d_in[4];
    const float* b2  = (const float*)d_in[5];
    const float* W3  = (const float*)d_in[6];
    const float* b3  = (const float*)d_in[7];
    const float* W4  = (const float*)d_in[8];
    const float* b4  = (const float*)d_in[9];
    const float* We  = (const float*)d_in[10];
    const float* be  = (const float*)d_in[11];
    const float* vg  = (const float*)d_in[12];
    const float* vb  = (const float*)d_in[13];
    const float* eg  = (const float*)d_in[14];
    const float* ebt = (const float*)d_in[15];
    const int*   ei  = (const int*)d_in[16];
    const int* srcp = ei;
    const int* dstp = ei + N_EDGES;
    float* out = (float*)d_out;

    cudaFuncSetAttribute(edge_pass1, cudaFuncAttributeMaxDynamicSharedMemorySize, EDGE_SMEM);

    prepack<<<16, 256>>>(W1, W2, W3, W4, We, b1, b2, b3, b4);
    node_gemm<<<296, 256>>>(x);
    edge_pass1<<<296, 256, EDGE_SMEM>>>(ea, srcp, dstp, be);
    node_stats<<<NS_BLOCKS, 256>>>();
    apply_fused<<<APPLY_NODE_BLOCKS + APPLY_EDGE_BLOCKS, 256>>>(x, ea, vg, vb, eg, ebt, out);
}